// round 1
// baseline (speedup 1.0000x reference)
#include <cuda_runtime.h>

#define BB   32
#define CC   1024
#define NSEQ 256
#define DQ   64
#define EPS_BN 1e-5f

typedef unsigned long long u64;

// ---- scratch (static device memory: allowed; no allocations) ----
__device__ float g_q[(size_t)BB * DQ * CC];          //  8 MB
__device__ float g_k[(size_t)BB * DQ * CC];          //  8 MB
__device__ float g_v[(size_t)BB * CC * NSEQ];        // 32 MB
__device__ float g_aff[(size_t)BB * CC * CC];        // 128 MB

// ---- packed f32x2 helpers (FFMA2 path: 2x fp32 throughput) ----
__device__ __forceinline__ u64 pack2(float a, float b) {
    u64 r; asm("mov.b64 %0, {%1,%2};" : "=l"(r) : "f"(a), "f"(b)); return r;
}
__device__ __forceinline__ void unpack2(u64 v, float& a, float& b) {
    asm("mov.b64 {%0,%1}, %2;" : "=f"(a), "=f"(b) : "l"(v));
}
__device__ __forceinline__ u64 fma2(u64 a, u64 b, u64 c) {
    u64 d; asm("fma.rn.f32x2 %0, %1, %2, %3;" : "=l"(d) : "l"(a), "l"(b), "l"(c)); return d;
}

// =====================================================================
// Kernel 1: q,k = relu(bn(W . x^T))   (per batch: [64,256] x [256,1024])
// block: 32 c-cols x all 64 o-rows, both q and k. grid (CC/32, BB)
// =====================================================================
__global__ __launch_bounds__(256) void qk_kernel(
    const float* __restrict__ x,
    const float* __restrict__ Wq, const float* __restrict__ Wk,
    const float* __restrict__ g1, const float* __restrict__ b1,
    const float* __restrict__ m1, const float* __restrict__ v1,
    const float* __restrict__ g2, const float* __restrict__ b2,
    const float* __restrict__ m2, const float* __restrict__ v2)
{
    __shared__ __align__(16) float Wqs[DQ * 64];
    __shared__ __align__(16) float Wks[DQ * 64];
    __shared__ __align__(16) float Xs[32 * 68];   // padded stride 68

    const int tid = threadIdx.x;
    const int b   = blockIdx.y;
    const int c0  = blockIdx.x * 32;
    const int cl  = tid & 31;
    const int og  = tid >> 5;          // 0..7

    float accq[8], acck[8];
#pragma unroll
    for (int i = 0; i < 8; i++) { accq[i] = 0.f; acck[i] = 0.f; }

    for (int nk = 0; nk < NSEQ; nk += 64) {
        __syncthreads();
#pragma unroll
        for (int idx = tid; idx < DQ * 64; idx += 256) {
            int o = idx >> 6, nn = idx & 63;
            Wqs[idx] = Wq[o * NSEQ + nk + nn];
            Wks[idx] = Wk[o * NSEQ + nk + nn];
        }
#pragma unroll
        for (int idx = tid; idx < 32 * 64; idx += 256) {
            int r = idx >> 6, nn = idx & 63;
            Xs[r * 68 + nn] = x[((size_t)b * CC + c0 + r) * NSEQ + nk + nn];
        }
        __syncthreads();
#pragma unroll
        for (int nn4 = 0; nn4 < 64; nn4 += 4) {
            float4 xv = *(const float4*)&Xs[cl * 68 + nn4];
#pragma unroll
            for (int i = 0; i < 8; i++) {
                int o = og + 8 * i;
                float4 wq = *(const float4*)&Wqs[o * 64 + nn4];
                float4 wk = *(const float4*)&Wks[o * 64 + nn4];
                accq[i] += wq.x * xv.x + wq.y * xv.y + wq.z * xv.z + wq.w * xv.w;
                acck[i] += wk.x * xv.x + wk.y * xv.y + wk.z * xv.z + wk.w * xv.w;
            }
        }
    }

    const int c = c0 + cl;
#pragma unroll
    for (int i = 0; i < 8; i++) {
        int o = og + 8 * i;
        float s1 = g1[o] * rsqrtf(v1[o] + EPS_BN);
        float q  = (accq[i] - m1[o]) * s1 + b1[o];
        g_q[((size_t)b * DQ + o) * CC + c] = fmaxf(q, 0.f);
        float s2 = g2[o] * rsqrtf(v2[o] + EPS_BN);
        float k  = (acck[i] - m2[o]) * s2 + b2[o];
        g_k[((size_t)b * DQ + o) * CC + c] = fmaxf(k, 0.f);
    }
}

// =====================================================================
// Kernel 2: sim[c,d] = sum_o k[o,c] q[o,d];  aff = softmax(-sim) over d
// (softmax(max - sim) == softmax(-sim), shift invariant)
// block: 16 c-rows x full 1024 d.  grid (CC/16, BB)
// =====================================================================
__global__ __launch_bounds__(256) void sim_softmax_kernel()
{
    __shared__ float ks[DQ * 16];
    __shared__ float red[16 * 256];

    const int tid = threadIdx.x;
    const int b   = blockIdx.y;
    const int c0  = blockIdx.x * 16;

    for (int idx = tid; idx < DQ * 16; idx += 256) {
        int o = idx >> 4, cl = idx & 15;
        ks[idx] = g_k[((size_t)b * DQ + o) * CC + c0 + cl];
    }
    __syncthreads();

    const u64* q2 = (const u64*)(g_q + (size_t)b * DQ * CC);

    u64 acc[16][2];
#pragma unroll
    for (int cl = 0; cl < 16; cl++) { acc[cl][0] = 0ull; acc[cl][1] = 0ull; }

#pragma unroll 4
    for (int o = 0; o < DQ; o++) {
        u64 q0 = q2[o * 512 + tid];
        u64 q1 = q2[o * 512 + 256 + tid];
#pragma unroll
        for (int cl = 0; cl < 16; cl++) {
            float kv = ks[o * 16 + cl];
            u64 kp = pack2(kv, kv);
            acc[cl][0] = fma2(kp, q0, acc[cl][0]);
            acc[cl][1] = fma2(kp, q1, acc[cl][1]);
        }
    }

    float z[16][4];
#pragma unroll
    for (int cl = 0; cl < 16; cl++) {
        unpack2(acc[cl][0], z[cl][0], z[cl][1]);
        unpack2(acc[cl][1], z[cl][2], z[cl][3]);
        z[cl][0] = -z[cl][0]; z[cl][1] = -z[cl][1];
        z[cl][2] = -z[cl][2]; z[cl][3] = -z[cl][3];
    }

    // row max
#pragma unroll
    for (int cl = 0; cl < 16; cl++)
        red[cl * 256 + tid] = fmaxf(fmaxf(z[cl][0], z[cl][1]), fmaxf(z[cl][2], z[cl][3]));
    for (int s = 128; s > 0; s >>= 1) {
        __syncthreads();
        if (tid < s) {
#pragma unroll
            for (int cl = 0; cl < 16; cl++)
                red[cl * 256 + tid] = fmaxf(red[cl * 256 + tid], red[cl * 256 + tid + s]);
        }
    }
    __syncthreads();
    float rmax[16];
#pragma unroll
    for (int cl = 0; cl < 16; cl++) rmax[cl] = red[cl * 256];
    __syncthreads();

    // exp + row sum
#pragma unroll
    for (int cl = 0; cl < 16; cl++) {
        z[cl][0] = __expf(z[cl][0] - rmax[cl]);
        z[cl][1] = __expf(z[cl][1] - rmax[cl]);
        z[cl][2] = __expf(z[cl][2] - rmax[cl]);
        z[cl][3] = __expf(z[cl][3] - rmax[cl]);
        red[cl * 256 + tid] = z[cl][0] + z[cl][1] + z[cl][2] + z[cl][3];
    }
    for (int s = 128; s > 0; s >>= 1) {
        __syncthreads();
        if (tid < s) {
#pragma unroll
            for (int cl = 0; cl < 16; cl++)
                red[cl * 256 + tid] += red[cl * 256 + tid + s];
        }
    }
    __syncthreads();

    u64* aff2 = (u64*)(g_aff + (size_t)b * CC * CC);
#pragma unroll
    for (int cl = 0; cl < 16; cl++) {
        float inv = 1.0f / red[cl * 256];
        size_t base = (size_t)(c0 + cl) * 512;
        aff2[base + tid]       = pack2(z[cl][0] * inv, z[cl][1] * inv);
        aff2[base + 256 + tid] = pack2(z[cl][2] * inv, z[cl][3] * inv);
    }
}

// =====================================================================
// Kernel 3/4: SGEMM 1024x256x1024 per batch, 128x128 tile, kc=8,
// 8x8 micro-tile with f32x2 packed accumulators.
// MODE 0: v = relu(bn3(Wv . x[b]))           -> g_v
// MODE 1: out = alpha*(aff[b] . v[b]) + x    -> d_out
// grid (NSEQ/128, CC/128, BB)
// =====================================================================
template<int MODE>
__global__ __launch_bounds__(256) void gemm_kernel(
    const float* __restrict__ A_ext, const float* __restrict__ B_ext,
    float* __restrict__ C_ext, const float* __restrict__ xres,
    const float* __restrict__ g3, const float* __restrict__ b3,
    const float* __restrict__ m3, const float* __restrict__ v3,
    const float* __restrict__ alpha)
{
    __shared__ __align__(16) float As[8 * 128];
    __shared__ __align__(16) float Bs[8 * 128];

    const int tid = threadIdx.x;
    const int tx  = tid & 15, ty = tid >> 4;
    const int b   = blockIdx.z;
    const int m0  = blockIdx.y * 128;
    const int n0  = blockIdx.x * 128;

    const float* A;  const float* Bm;  float* Cm;
    if (MODE == 0) {
        A  = A_ext;                               // Wv [1024,1024]
        Bm = B_ext + (size_t)b * CC * NSEQ;       // x[b]
        Cm = g_v   + (size_t)b * CC * NSEQ;
    } else {
        A  = g_aff + (size_t)b * CC * CC;         // aff[b]
        Bm = g_v   + (size_t)b * CC * NSEQ;       // v[b]
        Cm = C_ext + (size_t)b * CC * NSEQ;       // d_out
    }

    const int lr  = tid >> 1, lh = tid & 1;       // A-tile loader coords
    const int bkk = tid >> 5, bnn = (tid & 31) * 4;

    u64 acc[8][4];
#pragma unroll
    for (int i = 0; i < 8; i++)
#pragma unroll
        for (int j = 0; j < 4; j++) acc[i][j] = 0ull;

    float4 av = *(const float4*)&A[(size_t)(m0 + lr) * CC + lh * 4];
    float4 bv = *(const float4*)&Bm[(size_t)bkk * NSEQ + n0 + bnn];

    for (int k0 = 0; k0 < CC; k0 += 8) {
        __syncthreads();
        As[(lh * 4 + 0) * 128 + lr] = av.x;
        As[(lh * 4 + 1) * 128 + lr] = av.y;
        As[(lh * 4 + 2) * 128 + lr] = av.z;
        As[(lh * 4 + 3) * 128 + lr] = av.w;
        *(float4*)&Bs[bkk * 128 + bnn] = bv;
        __syncthreads();
        if (k0 + 8 < CC) {
            av = *(const float4*)&A[(size_t)(m0 + lr) * CC + (k0 + 8) + lh * 4];
            bv = *(const float4*)&Bm[(size_t)(k0 + 8 + bkk) * NSEQ + n0 + bnn];
        }
#pragma unroll
        for (int kk = 0; kk < 8; kk++) {
            float4 a0 = *(const float4*)&As[kk * 128 + ty * 4];
            float4 a1 = *(const float4*)&As[kk * 128 + 64 + ty * 4];
            const u64* Bu = (const u64*)&Bs[kk * 128];
            u64 bp0 = Bu[tx * 4 + 0];
            u64 bp1 = Bu[tx * 4 + 1];
            u64 bp2 = Bu[tx * 4 + 2];
            u64 bp3 = Bu[tx * 4 + 3];
            u64 ap;
            ap = pack2(a0.x, a0.x);
            acc[0][0] = fma2(ap, bp0, acc[0][0]); acc[0][1] = fma2(ap, bp1, acc[0][1]);
            acc[0][2] = fma2(ap, bp2, acc[0][2]); acc[0][3] = fma2(ap, bp3, acc[0][3]);
            ap = pack2(a0.y, a0.y);
            acc[1][0] = fma2(ap, bp0, acc[1][0]); acc[1][1] = fma2(ap, bp1, acc[1][1]);
            acc[1][2] = fma2(ap, bp2, acc[1][2]); acc[1][3] = fma2(ap, bp3, acc[1][3]);
            ap = pack2(a0.z, a0.z);
            acc[2][0] = fma2(ap, bp0, acc[2][0]); acc[2][1] = fma2(ap, bp1, acc[2][1]);
            acc[2][2] = fma2(ap, bp2, acc[2][2]); acc[2][3] = fma2(ap, bp3, acc[2][3]);
            ap = pack2(a0.w, a0.w);
            acc[3][0] = fma2(ap, bp0, acc[3][0]); acc[3][1] = fma2(ap, bp1, acc[3][1]);
            acc[3][2] = fma2(ap, bp2, acc[3][2]); acc[3][3] = fma2(ap, bp3, acc[3][3]);
            ap = pack2(a1.x, a1.x);
            acc[4][0] = fma2(ap, bp0, acc[4][0]); acc[4][1] = fma2(ap, bp1, acc[4][1]);
            acc[4][2] = fma2(ap, bp2, acc[4][2]); acc[4][3] = fma2(ap, bp3, acc[4][3]);
            ap = pack2(a1.y, a1.y);
            acc[5][0] = fma2(ap, bp0, acc[5][0]); acc[5][1] = fma2(ap, bp1, acc[5][1]);
            acc[5][2] = fma2(ap, bp2, acc[5][2]); acc[5][3] = fma2(ap, bp3, acc[5][3]);
            ap = pack2(a1.z, a1.z);
            acc[6][0] = fma2(ap, bp0, acc[6][0]); acc[6][1] = fma2(ap, bp1, acc[6][1]);
            acc[6][2] = fma2(ap, bp2, acc[6][2]); acc[6][3] = fma2(ap, bp3, acc[6][3]);
            ap = pack2(a1.w, a1.w);
            acc[7][0] = fma2(ap, bp0, acc[7][0]); acc[7][1] = fma2(ap, bp1, acc[7][1]);
            acc[7][2] = fma2(ap, bp2, acc[7][2]); acc[7][3] = fma2(ap, bp3, acc[7][3]);
        }
    }

    float a_scale = 0.f;
    if (MODE == 1) a_scale = alpha[0];

#pragma unroll
    for (int i = 0; i < 8; i++) {
        int mi = m0 + ((i < 4) ? (ty * 4 + i) : (64 + ty * 4 + (i - 4)));
        float cv[8];
        unpack2(acc[i][0], cv[0], cv[1]);
        unpack2(acc[i][1], cv[2], cv[3]);
        unpack2(acc[i][2], cv[4], cv[5]);
        unpack2(acc[i][3], cv[6], cv[7]);
        if (MODE == 0) {
            float s  = g3[mi] * rsqrtf(v3[mi] + EPS_BN);
            float bb = b3[mi] - m3[mi] * s;
#pragma unroll
            for (int j = 0; j < 8; j++) cv[j] = fmaxf(cv[j] * s + bb, 0.f);
        } else {
            const float4 x0 = *(const float4*)&xres[((size_t)b * CC + mi) * NSEQ + n0 + tx * 8];
            const float4 x1 = *(const float4*)&xres[((size_t)b * CC + mi) * NSEQ + n0 + tx * 8 + 4];
            cv[0] = a_scale * cv[0] + x0.x; cv[1] = a_scale * cv[1] + x0.y;
            cv[2] = a_scale * cv[2] + x0.z; cv[3] = a_scale * cv[3] + x0.w;
            cv[4] = a_scale * cv[4] + x1.x; cv[5] = a_scale * cv[5] + x1.y;
            cv[6] = a_scale * cv[6] + x1.z; cv[7] = a_scale * cv[7] + x1.w;
        }
        *(float4*)&Cm[(size_t)mi * NSEQ + n0 + tx * 8]     = make_float4(cv[0], cv[1], cv[2], cv[3]);
        *(float4*)&Cm[(size_t)mi * NSEQ + n0 + tx * 8 + 4] = make_float4(cv[4], cv[5], cv[6], cv[7]);
    }
}

// =====================================================================
extern "C" void kernel_launch(void* const* d_in, const int* in_sizes, int n_in,
                              void* d_out, int out_size)
{
    const float* x    = (const float*)d_in[0];
    const float* Wq   = (const float*)d_in[1];
    const float* Wk   = (const float*)d_in[2];
    const float* Wv   = (const float*)d_in[3];
    const float* bn1g = (const float*)d_in[4];
    const float* bn1b = (const float*)d_in[5];
    const float* bn1m = (const float*)d_in[6];
    const float* bn1v = (const float*)d_in[7];
    const float* bn2g = (const float*)d_in[8];
    const float* bn2b = (const float*)d_in[9];
    const float* bn2m = (const float*)d_in[10];
    const float* bn2v = (const float*)d_in[11];
    const float* bn3g = (const float*)d_in[12];
    const float* bn3b = (const float*)d_in[13];
    const float* bn3m = (const float*)d_in[14];
    const float* bn3v = (const float*)d_in[15];
    const float* alpha= (const float*)d_in[16];
    float* out = (float*)d_out;

    qk_kernel<<<dim3(CC / 32, BB), 256>>>(x, Wq, Wk,
                                          bn1g, bn1b, bn1m, bn1v,
                                          bn2g, bn2b, bn2m, bn2v);

    gemm_kernel<0><<<dim3(NSEQ / 128, CC / 128, BB), 256>>>(
        Wv, x, nullptr, nullptr, bn3g, bn3b, bn3m, bn3v, nullptr);

    sim_softmax_kernel<<<dim3(CC / 16, BB), 256>>>();

    gemm_kernel<1><<<dim3(NSEQ / 128, CC / 128, BB), 256>>>(
        nullptr, nullptr, out, x, nullptr, nullptr, nullptr, nullptr, alpha);
}

// round 3
// speedup vs baseline: 1.9002x; 1.9002x over previous
#include <cuda_runtime.h>
#include <cuda_bf16.h>
#include <cstdint>

#define BB   32
#define CC   1024
#define NSEQ 256
#define DQ   64
#define EPS_BN 1e-5f

typedef unsigned long long u64;
typedef unsigned int u32;

// ---------------- scratch (static device memory) ----------------
__device__ float g_q[(size_t)BB * DQ * CC];                 // 8 MB
__device__ float g_k[(size_t)BB * DQ * CC];                 // 8 MB
__device__ __nv_bfloat16 g_wv_hi[(size_t)CC * CC];          // 2 MB
__device__ __nv_bfloat16 g_wv_lo[(size_t)CC * CC];          // 2 MB
__device__ __nv_bfloat16 g_xT_hi[(size_t)BB * NSEQ * CC];   // 16 MB
__device__ __nv_bfloat16 g_xT_lo[(size_t)BB * NSEQ * CC];   // 16 MB
__device__ __nv_bfloat16 g_vT_hi[(size_t)BB * NSEQ * CC];   // 16 MB
__device__ __nv_bfloat16 g_vT_lo[(size_t)BB * NSEQ * CC];   // 16 MB
__device__ __nv_bfloat16 g_aff_hi[(size_t)BB * CC * CC];    // 64 MB
__device__ __nv_bfloat16 g_aff_lo[(size_t)BB * CC * CC];    // 64 MB

// ---------------- helpers ----------------
__device__ __forceinline__ u32 smem_u32(const void* p) {
    u32 a;
    asm("{ .reg .u64 t; cvta.to.shared.u64 t, %1; cvt.u32.u64 %0, t; }"
        : "=r"(a) : "l"(p));
    return a;
}
__device__ __forceinline__ u64 pack2(float a, float b) {
    u64 r; asm("mov.b64 %0, {%1,%2};" : "=l"(r) : "f"(a), "f"(b)); return r;
}
__device__ __forceinline__ void unpack2(u64 v, float& a, float& b) {
    asm("mov.b64 {%0,%1}, %2;" : "=f"(a), "=f"(b) : "l"(v));
}
__device__ __forceinline__ u64 fma2(u64 a, u64 b, u64 c) {
    u64 d; asm("fma.rn.f32x2 %0, %1, %2, %3;" : "=l"(d) : "l"(a), "l"(b), "l"(c)); return d;
}
__device__ __forceinline__ void split_bf16(float v, __nv_bfloat16& h, __nv_bfloat16& l) {
    h = __float2bfloat16(v);
    l = __float2bfloat16(v - __bfloat162float(h));
}

__device__ __forceinline__ void cp16(u32 dst, const void* src) {
    asm volatile("cp.async.cg.shared.global [%0], [%1], 16;" :: "r"(dst), "l"(src));
}
__device__ __forceinline__ void cp_commit() {
    asm volatile("cp.async.commit_group;" ::: "memory");
}
__device__ __forceinline__ void cp_wait1() {
    asm volatile("cp.async.wait_group 1;" ::: "memory");
}
__device__ __forceinline__ void cp_wait0() {
    asm volatile("cp.async.wait_group 0;" ::: "memory");
}

__device__ __forceinline__ void ldsm4(u32 addr, u32& r0, u32& r1, u32& r2, u32& r3) {
    asm volatile("ldmatrix.sync.aligned.m8n8.x4.shared.b16 {%0,%1,%2,%3}, [%4];"
                 : "=r"(r0), "=r"(r1), "=r"(r2), "=r"(r3) : "r"(addr));
}

__device__ __forceinline__ void mma_bf16(float* c, const u32* a, u32 b0, u32 b1) {
    asm volatile(
        "mma.sync.aligned.m16n8k16.row.col.f32.bf16.bf16.f32 "
        "{%0,%1,%2,%3}, {%4,%5,%6,%7}, {%8,%9}, {%0,%1,%2,%3};"
        : "+f"(c[0]), "+f"(c[1]), "+f"(c[2]), "+f"(c[3])
        : "r"(a[0]), "r"(a[1]), "r"(a[2]), "r"(a[3]), "r"(b0), "r"(b1));
}

// =====================================================================
// Kernel 1: q,k = relu(bn(W . x^T))
// =====================================================================
__global__ __launch_bounds__(256) void qk_kernel(
    const float* __restrict__ x,
    const float* __restrict__ Wq, const float* __restrict__ Wk,
    const float* __restrict__ g1, const float* __restrict__ b1,
    const float* __restrict__ m1, const float* __restrict__ v1,
    const float* __restrict__ g2, const float* __restrict__ b2,
    const float* __restrict__ m2, const float* __restrict__ v2)
{
    __shared__ __align__(16) float Wqs[DQ * 64];
    __shared__ __align__(16) float Wks[DQ * 64];
    __shared__ __align__(16) float Xs[32 * 68];

    const int tid = threadIdx.x;
    const int b   = blockIdx.y;
    const int c0  = blockIdx.x * 32;
    const int cl  = tid & 31;
    const int og  = tid >> 5;

    float accq[8], acck[8];
#pragma unroll
    for (int i = 0; i < 8; i++) { accq[i] = 0.f; acck[i] = 0.f; }

    for (int nk = 0; nk < NSEQ; nk += 64) {
        __syncthreads();
#pragma unroll
        for (int idx = tid; idx < DQ * 64; idx += 256) {
            int o = idx >> 6, nn = idx & 63;
            Wqs[idx] = Wq[o * NSEQ + nk + nn];
            Wks[idx] = Wk[o * NSEQ + nk + nn];
        }
#pragma unroll
        for (int idx = tid; idx < 32 * 64; idx += 256) {
            int r = idx >> 6, nn = idx & 63;
            Xs[r * 68 + nn] = x[((size_t)b * CC + c0 + r) * NSEQ + nk + nn];
        }
        __syncthreads();
#pragma unroll
        for (int nn4 = 0; nn4 < 64; nn4 += 4) {
            float4 xv = *(const float4*)&Xs[cl * 68 + nn4];
#pragma unroll
            for (int i = 0; i < 8; i++) {
                int o = og + 8 * i;
                float4 wq = *(const float4*)&Wqs[o * 64 + nn4];
                float4 wk = *(const float4*)&Wks[o * 64 + nn4];
                accq[i] += wq.x * xv.x + wq.y * xv.y + wq.z * xv.z + wq.w * xv.w;
                acck[i] += wk.x * xv.x + wk.y * xv.y + wk.z * xv.z + wk.w * xv.w;
            }
        }
    }

    const int c = c0 + cl;
#pragma unroll
    for (int i = 0; i < 8; i++) {
        int o = og + 8 * i;
        float s1 = g1[o] * rsqrtf(v1[o] + EPS_BN);
        float q  = (accq[i] - m1[o]) * s1 + b1[o];
        g_q[((size_t)b * DQ + o) * CC + c] = fmaxf(q, 0.f);
        float s2 = g2[o] * rsqrtf(v2[o] + EPS_BN);
        float k  = (acck[i] - m2[o]) * s2 + b2[o];
        g_k[((size_t)b * DQ + o) * CC + c] = fmaxf(k, 0.f);
    }
}

// =====================================================================
// Kernel 2: sim + softmax(-sim); writes aff as bf16 hi/lo [c][d]
// =====================================================================
__global__ __launch_bounds__(256) void sim_softmax_kernel()
{
    __shared__ float ks[DQ * 16];
    __shared__ float red[16 * 256];

    const int tid = threadIdx.x;
    const int b   = blockIdx.y;
    const int c0  = blockIdx.x * 16;

    for (int idx = tid; idx < DQ * 16; idx += 256) {
        int o = idx >> 4, cl = idx & 15;
        ks[idx] = g_k[((size_t)b * DQ + o) * CC + c0 + cl];
    }
    __syncthreads();

    const u64* q2 = (const u64*)(g_q + (size_t)b * DQ * CC);

    u64 acc[16][2];
#pragma unroll
    for (int cl = 0; cl < 16; cl++) { acc[cl][0] = 0ull; acc[cl][1] = 0ull; }

#pragma unroll 4
    for (int o = 0; o < DQ; o++) {
        u64 q0 = q2[o * 512 + tid];
        u64 q1 = q2[o * 512 + 256 + tid];
#pragma unroll
        for (int cl = 0; cl < 16; cl++) {
            float kv = ks[o * 16 + cl];
            u64 kp = pack2(kv, kv);
            acc[cl][0] = fma2(kp, q0, acc[cl][0]);
            acc[cl][1] = fma2(kp, q1, acc[cl][1]);
        }
    }

    float z[16][4];
#pragma unroll
    for (int cl = 0; cl < 16; cl++) {
        unpack2(acc[cl][0], z[cl][0], z[cl][1]);
        unpack2(acc[cl][1], z[cl][2], z[cl][3]);
        z[cl][0] = -z[cl][0]; z[cl][1] = -z[cl][1];
        z[cl][2] = -z[cl][2]; z[cl][3] = -z[cl][3];
    }

#pragma unroll
    for (int cl = 0; cl < 16; cl++)
        red[cl * 256 + tid] = fmaxf(fmaxf(z[cl][0], z[cl][1]), fmaxf(z[cl][2], z[cl][3]));
    for (int s = 128; s > 0; s >>= 1) {
        __syncthreads();
        if (tid < s) {
#pragma unroll
            for (int cl = 0; cl < 16; cl++)
                red[cl * 256 + tid] = fmaxf(red[cl * 256 + tid], red[cl * 256 + tid + s]);
        }
    }
    __syncthreads();
    float rmax[16];
#pragma unroll
    for (int cl = 0; cl < 16; cl++) rmax[cl] = red[cl * 256];
    __syncthreads();

#pragma unroll
    for (int cl = 0; cl < 16; cl++) {
        z[cl][0] = __expf(z[cl][0] - rmax[cl]);
        z[cl][1] = __expf(z[cl][1] - rmax[cl]);
        z[cl][2] = __expf(z[cl][2] - rmax[cl]);
        z[cl][3] = __expf(z[cl][3] - rmax[cl]);
        red[cl * 256 + tid] = z[cl][0] + z[cl][1] + z[cl][2] + z[cl][3];
    }
    for (int s = 128; s > 0; s >>= 1) {
        __syncthreads();
        if (tid < s) {
#pragma unroll
            for (int cl = 0; cl < 16; cl++)
                red[cl * 256 + tid] += red[cl * 256 + tid + s];
        }
    }
    __syncthreads();

    __nv_bfloat162* affh = (__nv_bfloat162*)g_aff_hi + (size_t)b * CC * CC / 2;
    __nv_bfloat162* affl = (__nv_bfloat162*)g_aff_lo + (size_t)b * CC * CC / 2;
#pragma unroll
    for (int cl = 0; cl < 16; cl++) {
        float inv = 1.0f / red[cl * 256];
        size_t rb = (size_t)(c0 + cl) * 512;
        float a0 = z[cl][0] * inv, a1 = z[cl][1] * inv;
        float a2 = z[cl][2] * inv, a3 = z[cl][3] * inv;
        __nv_bfloat16 h0, l0, h1, l1, h2, l2, h3, l3;
        split_bf16(a0, h0, l0); split_bf16(a1, h1, l1);
        split_bf16(a2, h2, l2); split_bf16(a3, h3, l3);
        __nv_bfloat162 hh0; hh0.x = h0; hh0.y = h1;
        __nv_bfloat162 hh1; hh1.x = h2; hh1.y = h3;
        __nv_bfloat162 ll0; ll0.x = l0; ll0.y = l1;
        __nv_bfloat162 ll1; ll1.x = l2; ll1.y = l3;
        affh[rb + tid]       = hh0;
        affh[rb + 256 + tid] = hh1;
        affl[rb + tid]       = ll0;
        affl[rb + 256 + tid] = ll1;
    }
}

// =====================================================================
// converts
// =====================================================================
__global__ __launch_bounds__(256) void convert_wv(const float* __restrict__ W)
{
    size_t i = (size_t)blockIdx.x * 256 + threadIdx.x;
    float4 v = ((const float4*)W)[i];
    __nv_bfloat16 h0, l0, h1, l1, h2, l2, h3, l3;
    split_bf16(v.x, h0, l0); split_bf16(v.y, h1, l1);
    split_bf16(v.z, h2, l2); split_bf16(v.w, h3, l3);
    __nv_bfloat162* hp = (__nv_bfloat162*)g_wv_hi;
    __nv_bfloat162* lp = (__nv_bfloat162*)g_wv_lo;
    __nv_bfloat162 a; a.x = h0; a.y = h1;
    __nv_bfloat162 bq; bq.x = h2; bq.y = h3;
    hp[i * 2] = a; hp[i * 2 + 1] = bq;
    a.x = l0; a.y = l1; bq.x = l2; bq.y = l3;
    lp[i * 2] = a; lp[i * 2 + 1] = bq;
}

__global__ void convert_xT(const float* __restrict__ x)
{
    __shared__ float t[32][33];
    const int tx = threadIdx.x, ty = threadIdx.y;
    const int c0 = blockIdx.x * 32, n0 = blockIdx.y * 32, b = blockIdx.z;

#pragma unroll
    for (int r = 0; r < 4; r++) {
        int row = ty + r * 8;
        t[row][tx] = x[((size_t)b * CC + c0 + row) * NSEQ + n0 + tx];
    }
    __syncthreads();
#pragma unroll
    for (int r = 0; r < 4; r++) {
        int nrow = ty + r * 8;
        float val = t[tx][nrow];
        __nv_bfloat16 h, l; split_bf16(val, h, l);
        size_t off = ((size_t)b * NSEQ + n0 + nrow) * CC + c0 + tx;
        g_xT_hi[off] = h;
        g_xT_lo[off] = l;
    }
}

// =====================================================================
// mma.sync bf16x3 GEMM: C[128 x 256] tile, K=1024, slab=64, double buf.
// A row-major [M][K] hi/lo, B K-major [N][K] hi/lo.
// MODE 0: A=Wv, B=xT  -> v = relu(bn3(.)), store transposed vT hi/lo
// MODE 1: A=aff, B=vT -> out = alpha*(.) + x, store [b][c][n] fp32
// grid (CC/128, BB), 256 threads (8 warps = 2M x 4N), warp tile 64x64
// =====================================================================
#define STAGE_BYTES 98304     // A 32KB (hi+lo) + B 64KB (hi+lo)
#define SMEM_BYTES  (2 * STAGE_BYTES)

template<int MODE>
__global__ void __launch_bounds__(256, 1) mma_gemm(
    float* __restrict__ Cout, const float* __restrict__ xres,
    const float* __restrict__ g3, const float* __restrict__ b3,
    const float* __restrict__ m3, const float* __restrict__ v3,
    const float* __restrict__ alpha)
{
    extern __shared__ __align__(1024) char smem[];
    const u32 sbase = smem_u32(smem);
    const int tid  = threadIdx.x;
    const int b    = blockIdx.y;
    const int m0   = blockIdx.x * 128;

    const __nv_bfloat16 *A_hi, *A_lo, *B_hi, *B_lo;
    if (MODE == 0) {
        A_hi = g_wv_hi;  A_lo = g_wv_lo;
        B_hi = g_xT_hi + (size_t)b * NSEQ * CC;
        B_lo = g_xT_lo + (size_t)b * NSEQ * CC;
    } else {
        A_hi = g_aff_hi + (size_t)b * CC * CC;
        A_lo = g_aff_lo + (size_t)b * CC * CC;
        B_hi = g_vT_hi + (size_t)b * NSEQ * CC;
        B_lo = g_vT_lo + (size_t)b * NSEQ * CC;
    }

    // --- loader lambda: slab k0 into stage buf ---
    auto load_slab = [&](int k0, int buf) {
        const u32 sb = sbase + buf * STAGE_BYTES;
#pragma unroll
        for (int i = 0; i < 4; i++) {            // A: 128 rows x 8 chunks
            int idx = tid + i * 256;
            int row = idx >> 3, c = idx & 7;
            u32 dst = sb + row * 128 + ((c ^ (row & 7)) << 4);
            const __nv_bfloat16* sh = A_hi + (size_t)(m0 + row) * CC + k0 + c * 8;
            const __nv_bfloat16* sl = A_lo + (size_t)(m0 + row) * CC + k0 + c * 8;
            cp16(dst, sh);
            cp16(dst + 16384, sl);
        }
#pragma unroll
        for (int i = 0; i < 8; i++) {            // B: 256 rows x 8 chunks
            int idx = tid + i * 256;
            int row = idx >> 3, c = idx & 7;
            u32 dst = sb + 32768 + row * 128 + ((c ^ (row & 7)) << 4);
            const __nv_bfloat16* sh = B_hi + (size_t)row * CC + k0 + c * 8;
            const __nv_bfloat16* sl = B_lo + (size_t)row * CC + k0 + c * 8;
            cp16(dst, sh);
            cp16(dst + 32768, sl);
        }
        cp_commit();
    };

    const int lane = tid & 31;
    const int lr   = lane & 7;
    const int sub  = lane >> 3;
    const int warp = tid >> 5;
    const int wm   = warp >> 2, wn = warp & 3;

    const int a_row = wm * 64 + lr + (sub & 1) * 8;     // + mt*16
    const int a_cad = sub >> 1;
    const int b_row = wn * 64 + lr + (sub >> 1) * 8;    // + np*16
    const int b_cad = sub & 1;

    float acc[4][8][4];
#pragma unroll
    for (int i = 0; i < 4; i++)
#pragma unroll
        for (int j = 0; j < 8; j++)
#pragma unroll
            for (int e = 0; e < 4; e++) acc[i][j][e] = 0.f;

    load_slab(0, 0);

    for (int s = 0; s < 16; s++) {
        if (s + 1 < 16) { load_slab((s + 1) * 64, (s + 1) & 1); cp_wait1(); }
        else            { cp_wait0(); }
        __syncthreads();

        const u32 sb = sbase + (s & 1) * STAGE_BYTES;
#pragma unroll
        for (int kk = 0; kk < 4; kk++) {
            u32 bh[4][4], bl[4][4];
#pragma unroll
            for (int np = 0; np < 4; np++) {
                u32 badr = sb + 32768 + (b_row + np * 16) * 128
                         + (((kk * 2 + b_cad) ^ lr) << 4);
                ldsm4(badr,          bh[np][0], bh[np][1], bh[np][2], bh[np][3]);
                ldsm4(badr + 32768,  bl[np][0], bl[np][1], bl[np][2], bl[np][3]);
            }
#pragma unroll
            for (int mt = 0; mt < 4; mt++) {
                u32 ah[4], al[4];
                u32 aadr = sb + (a_row + mt * 16) * 128
                         + (((kk * 2 + a_cad) ^ lr) << 4);
                ldsm4(aadr,          ah[0], ah[1], ah[2], ah[3]);
                ldsm4(aadr + 16384,  al[0], al[1], al[2], al[3]);
#pragma unroll
                for (int np = 0; np < 4; np++) {
                    mma_bf16(acc[mt][2 * np],     ah, bh[np][0], bh[np][1]);
                    mma_bf16(acc[mt][2 * np + 1], ah, bh[np][2], bh[np][3]);
                    mma_bf16(acc[mt][2 * np],     ah, bl[np][0], bl[np][1]);
                    mma_bf16(acc[mt][2 * np + 1], ah, bl[np][2], bl[np][3]);
                    mma_bf16(acc[mt][2 * np],     al, bh[np][0], bh[np][1]);
                    mma_bf16(acc[mt][2 * np + 1], al, bh[np][2], bh[np][3]);
                }
            }
        }
        __syncthreads();
    }

    // ---------------- epilogue ----------------
    if (MODE == 0) {
        // relu(bn3), split bf16, transpose to vT[n][m] via smem
        float s3a[4][2], b3a[4][2];
#pragma unroll
        for (int mt = 0; mt < 4; mt++)
#pragma unroll
            for (int h = 0; h < 2; h++) {
                int m = m0 + wm * 64 + mt * 16 + (lane >> 2) + h * 8;
                float sc = g3[m] * rsqrtf(v3[m] + EPS_BN);
                s3a[mt][h] = sc;
                b3a[mt][h] = b3[m] - m3[m] * sc;
            }

        __nv_bfloat16* Th = (__nv_bfloat16*)smem;
        __nv_bfloat16* Tl = (__nv_bfloat16*)(smem + 73728);
        const int mloc = wm * 64 + (lane >> 2);
        const int nbas = wn * 64 + (lane & 3) * 2;
#pragma unroll
        for (int mt = 0; mt < 4; mt++)
#pragma unroll
            for (int jj = 0; jj < 8; jj++) {
                int nn = nbas + jj * 8;
#pragma unroll
                for (int e = 0; e < 4; e++) {
                    int h = e >> 1, col = e & 1;
                    float val = fmaxf(acc[mt][jj][e] * s3a[mt][h] + b3a[mt][h], 0.f);
                    __nv_bfloat16 hi, lo; split_bf16(val, hi, lo);
                    int off = (nn + col) * 136 + mloc + mt * 16 + h * 8;
                    Th[off] = hi;
                    Tl[off] = lo;
                }
            }
        __syncthreads();
#pragma unroll
        for (int i = 0; i < 16; i++) {
            int idx = tid + i * 256;
            int n = idx >> 4, ch = idx & 15;
            uint4 hv = *(uint4*)&Th[n * 136 + ch * 8];
            uint4 lv = *(uint4*)&Tl[n * 136 + ch * 8];
            size_t dst = ((size_t)b * NSEQ + n) * CC + m0 + ch * 8;
            *(uint4*)&g_vT_hi[dst] = hv;
            *(uint4*)&g_vT_lo[dst] = lv;
        }
    } else {
        const float al_ = alpha[0];
        const int nbas = wn * 64 + (lane & 3) * 2;
#pragma unroll
        for (int mt = 0; mt < 4; mt++) {
            int m = m0 + wm * 64 + mt * 16 + (lane >> 2);
#pragma unroll
            for (int jj = 0; jj < 8; jj++) {
                int nn = nbas + jj * 8;
                size_t b0i = ((size_t)b * CC + m) * NSEQ + nn;
                size_t b1i = ((size_t)b * CC + m + 8) * NSEQ + nn;
                float2 x0 = *(const float2*)&xres[b0i];
                float2 x1 = *(const float2*)&xres[b1i];
                float2 o0, o1;
                o0.x = al_ * acc[mt][jj][0] + x0.x;
                o0.y = al_ * acc[mt][jj][1] + x0.y;
                o1.x = al_ * acc[mt][jj][2] + x1.x;
                o1.y = al_ * acc[mt][jj][3] + x1.y;
                *(float2*)&Cout[b0i] = o0;
                *(float2*)&Cout[b1i] = o1;
            }
        }
    }
}

// =====================================================================
extern "C" void kernel_launch(void* const* d_in, const int* in_sizes, int n_in,
                              void* d_out, int out_size)
{
    const float* x    = (const float*)d_in[0];
    const float* Wq   = (const float*)d_in[1];
    const float* Wk   = (const float*)d_in[2];
    const float* Wv   = (const float*)d_in[3];
    const float* bn1g = (const float*)d_in[4];
    const float* bn1b = (const float*)d_in[5];
    const float* bn1m = (const float*)d_in[6];
    const float* bn1v = (const float*)d_in[7];
    const float* bn2g = (const float*)d_in[8];
    const float* bn2b = (const float*)d_in[9];
    const float* bn2m = (const float*)d_in[10];
    const float* bn2v = (const float*)d_in[11];
    const float* bn3g = (const float*)d_in[12];
    const float* bn3b = (const float*)d_in[13];
    const float* bn3m = (const float*)d_in[14];
    const float* bn3v = (const float*)d_in[15];
    const float* alpha= (const float*)d_in[16];
    float* out = (float*)d_out;

    cudaFuncSetAttribute(mma_gemm<0>, cudaFuncAttributeMaxDynamicSharedMemorySize, SMEM_BYTES);
    cudaFuncSetAttribute(mma_gemm<1>, cudaFuncAttributeMaxDynamicSharedMemorySize, SMEM_BYTES);

    qk_kernel<<<dim3(CC / 32, BB), 256>>>(x, Wq, Wk,
                                          bn1g, bn1b, bn1m, bn1v,
                                          bn2g, bn2b, bn2m, bn2v);

    convert_wv<<<CC * CC / 4 / 256, 256>>>(Wv);
    convert_xT<<<dim3(CC / 32, NSEQ / 32, BB), dim3(32, 8)>>>(x);

    mma_gemm<0><<<dim3(CC / 128, BB), 256, SMEM_BYTES>>>(
        nullptr, nullptr, bn3g, bn3b, bn3m, bn3v, nullptr);

    sim_softmax_kernel<<<dim3(CC / 16, BB), 256>>>();

    mma_gemm<1><<<dim3(CC / 128, BB), 256, SMEM_BYTES>>>(
        out, x, nullptr, nullptr, nullptr, nullptr, alpha);
}

// round 4
// speedup vs baseline: 3.9078x; 2.0566x over previous
#include <cuda_runtime.h>
#include <cuda_bf16.h>
#include <cstdint>

#define BB   32
#define CC   1024
#define NSEQ 256
#define DQ   64
#define EPS_BN 1e-5f

typedef unsigned long long u64;
typedef unsigned int u32;

// ---------------- scratch (static device memory) ----------------
__device__ __nv_bfloat16 g_x_hi[(size_t)BB * CC * NSEQ];    // 16 MB  x[b][c][n]
__device__ __nv_bfloat16 g_x_lo[(size_t)BB * CC * NSEQ];    // 16 MB
__device__ __nv_bfloat16 g_xT_hi[(size_t)BB * NSEQ * CC];   // 16 MB  x^T[b][n][c]
__device__ __nv_bfloat16 g_wv_hi[(size_t)CC * CC];          //  2 MB
__device__ __nv_bfloat16 g_wv_lo[(size_t)CC * CC];          //  2 MB
__device__ __nv_bfloat16 g_wqk_hi[128 * NSEQ];              // 64 KB  [Wq;Wk]
__device__ __nv_bfloat16 g_wqk_lo[128 * NSEQ];
__device__ __nv_bfloat16 g_qT_hi[(size_t)BB * CC * DQ];     //  4 MB  q^T[b][c][o]
__device__ __nv_bfloat16 g_qT_lo[(size_t)BB * CC * DQ];
__device__ __nv_bfloat16 g_kT_hi[(size_t)BB * CC * DQ];
__device__ __nv_bfloat16 g_kT_lo[(size_t)BB * CC * DQ];
__device__ float         g_sim[(size_t)BB * CC * CC];       // 128 MB
__device__ __nv_bfloat16 g_aff_hi[(size_t)BB * CC * CC];    // 64 MB
__device__ __nv_bfloat16 g_aff_lo[(size_t)BB * CC * CC];    // 64 MB
__device__ __nv_bfloat16 g_vT_hi[(size_t)BB * NSEQ * CC];   // 16 MB  v^T[b][n][o]

// ---------------- helpers ----------------
__device__ __forceinline__ u32 smem_u32(const void* p) {
    u32 a;
    asm("{ .reg .u64 t; cvta.to.shared.u64 t, %1; cvt.u32.u64 %0, t; }"
        : "=r"(a) : "l"(p));
    return a;
}
__device__ __forceinline__ void split_bf16(float v, __nv_bfloat16& h, __nv_bfloat16& l) {
    h = __float2bfloat16(v);
    l = __float2bfloat16(v - __bfloat162float(h));
}
__device__ __forceinline__ void cp16(u32 dst, const void* src) {
    asm volatile("cp.async.cg.shared.global [%0], [%1], 16;" :: "r"(dst), "l"(src));
}
__device__ __forceinline__ void cp_commit() {
    asm volatile("cp.async.commit_group;" ::: "memory");
}
__device__ __forceinline__ void cp_wait1() {
    asm volatile("cp.async.wait_group 1;" ::: "memory");
}
__device__ __forceinline__ void cp_wait0() {
    asm volatile("cp.async.wait_group 0;" ::: "memory");
}
__device__ __forceinline__ void ldsm4(u32 addr, u32& r0, u32& r1, u32& r2, u32& r3) {
    asm volatile("ldmatrix.sync.aligned.m8n8.x4.shared.b16 {%0,%1,%2,%3}, [%4];"
                 : "=r"(r0), "=r"(r1), "=r"(r2), "=r"(r3) : "r"(addr));
}
__device__ __forceinline__ void mma_bf16(float* c, const u32* a, u32 b0, u32 b1) {
    asm volatile(
        "mma.sync.aligned.m16n8k16.row.col.f32.bf16.bf16.f32 "
        "{%0,%1,%2,%3}, {%4,%5,%6,%7}, {%8,%9}, {%0,%1,%2,%3};"
        : "+f"(c[0]), "+f"(c[1]), "+f"(c[2]), "+f"(c[3])
        : "r"(a[0]), "r"(a[1]), "r"(a[2]), "r"(a[3]), "r"(b0), "r"(b1));
}

// =====================================================================
// convert kernels
// =====================================================================
__global__ void convert_x(const float* __restrict__ x)
{
    __shared__ float t[32][33];
    const int tx = threadIdx.x, ty = threadIdx.y;
    const int c0 = blockIdx.x * 32, n0 = blockIdx.y * 32, b = blockIdx.z;

#pragma unroll
    for (int r = 0; r < 4; r++) {
        int row = ty + r * 8;
        size_t off = ((size_t)b * CC + c0 + row) * NSEQ + n0 + tx;
        float v = x[off];
        t[row][tx] = v;
        __nv_bfloat16 h, l; split_bf16(v, h, l);
        g_x_hi[off] = h;
        g_x_lo[off] = l;
    }
    __syncthreads();
#pragma unroll
    for (int r = 0; r < 4; r++) {
        int nrow = ty + r * 8;
        g_xT_hi[((size_t)b * NSEQ + n0 + nrow) * CC + c0 + tx] =
            __float2bfloat16(t[tx][nrow]);
    }
}

__global__ __launch_bounds__(256) void convert_wv(const float* __restrict__ W)
{
    size_t i = (size_t)blockIdx.x * 256 + threadIdx.x;
    float4 v = ((const float4*)W)[i];
    __nv_bfloat16 h0, l0, h1, l1, h2, l2, h3, l3;
    split_bf16(v.x, h0, l0); split_bf16(v.y, h1, l1);
    split_bf16(v.z, h2, l2); split_bf16(v.w, h3, l3);
    __nv_bfloat162* hp = (__nv_bfloat162*)g_wv_hi;
    __nv_bfloat162* lp = (__nv_bfloat162*)g_wv_lo;
    __nv_bfloat162 a; a.x = h0; a.y = h1;
    __nv_bfloat162 bq; bq.x = h2; bq.y = h3;
    hp[i * 2] = a; hp[i * 2 + 1] = bq;
    a.x = l0; a.y = l1; bq.x = l2; bq.y = l3;
    lp[i * 2] = a; lp[i * 2 + 1] = bq;
}

__global__ __launch_bounds__(256) void convert_wqk(
    const float* __restrict__ Wq, const float* __restrict__ Wk)
{
    int r = blockIdx.x;
    const float* src = (r < 64) ? (Wq + (size_t)r * NSEQ) : (Wk + (size_t)(r - 64) * NSEQ);
    float v = src[threadIdx.x];
    __nv_bfloat16 h, l; split_bf16(v, h, l);
    g_wqk_hi[r * NSEQ + threadIdx.x] = h;
    g_wqk_lo[r * NSEQ + threadIdx.x] = l;
}

// =====================================================================
// unified mma.sync GEMM: C[128 x 256] tile, slab=64, double buffered.
// A row-major [M][K] hi/lo; B K-major [Ntile rows][K] hi (+lo if PASSES==3).
// MODE 0: qk.  A=[Wq;Wk](128xK256)  B=x_hi/lo[c][n]   -> bn+relu, qT/kT hi/lo
// MODE 1: sim. A=kT(hi/lo)[c][64]   B=qT(hi/lo)[d][64] -> sim fp32
// MODE 2: v.   A=Wv(hi/lo)[o][c]    B=xT_hi[n][c]      -> bn3+relu, vT_hi
// MODE 3: out. A=aff(hi/lo)[c][d]   B=vT_hi[n][d]      -> alpha*.+x, d_out
// grid (N/256, M/128, BB)
// =====================================================================
template<int MODE, int PASSES, int KTOT>
__global__ void __launch_bounds__(256, 1) mma_gemm2(
    float* __restrict__ Cout, const float* __restrict__ xres,
    const float* __restrict__ gA, const float* __restrict__ bA,
    const float* __restrict__ mA, const float* __restrict__ vA,
    const float* __restrict__ gB, const float* __restrict__ bB,
    const float* __restrict__ mB, const float* __restrict__ vB,
    const float* __restrict__ alpha)
{
    constexpr int STAGE = (PASSES == 3) ? 98304 : 65536;
    constexpr int NSLAB = KTOT / 64;

    extern __shared__ __align__(1024) char smem[];
    const u32 sbase = smem_u32(smem);
    const int tid = threadIdx.x;
    const int b   = blockIdx.z;
    const int n0  = blockIdx.x * 256;
    const int m0  = blockIdx.y * 128;

    int lda, ldb;
    const __nv_bfloat16 *A_hi, *A_lo, *B_hi, *B_lo = nullptr;
    if (MODE == 0) {
        A_hi = g_wqk_hi; A_lo = g_wqk_lo;
        B_hi = g_x_hi + (size_t)b * CC * NSEQ;
        B_lo = g_x_lo + (size_t)b * CC * NSEQ;
        lda = NSEQ; ldb = NSEQ;
    } else if (MODE == 1) {
        A_hi = g_kT_hi + (size_t)b * CC * DQ;
        A_lo = g_kT_lo + (size_t)b * CC * DQ;
        B_hi = g_qT_hi + (size_t)b * CC * DQ;
        B_lo = g_qT_lo + (size_t)b * CC * DQ;
        lda = DQ; ldb = DQ;
    } else if (MODE == 2) {
        A_hi = g_wv_hi; A_lo = g_wv_lo;
        B_hi = g_xT_hi + (size_t)b * NSEQ * CC;
        lda = CC; ldb = CC;
    } else {
        A_hi = g_aff_hi + (size_t)b * CC * CC;
        A_lo = g_aff_lo + (size_t)b * CC * CC;
        B_hi = g_vT_hi + (size_t)b * NSEQ * CC;
        lda = CC; ldb = CC;
    }

    auto load_slab = [&](int k0, int buf) {
        const u32 sb = sbase + buf * STAGE;
#pragma unroll
        for (int i = 0; i < 4; i++) {               // A: 128 rows x 8 chunks
            int idx = tid + i * 256;
            int row = idx >> 3, c = idx & 7;
            u32 dst = sb + row * 128 + ((c ^ (row & 7)) << 4);
            cp16(dst,         A_hi + (size_t)(m0 + row) * lda + k0 + c * 8);
            cp16(dst + 16384, A_lo + (size_t)(m0 + row) * lda + k0 + c * 8);
        }
#pragma unroll
        for (int i = 0; i < 8; i++) {               // B: 256 rows x 8 chunks
            int idx = tid + i * 256;
            int row = idx >> 3, c = idx & 7;
            u32 dst = sb + 32768 + row * 128 + ((c ^ (row & 7)) << 4);
            cp16(dst, B_hi + (size_t)(n0 + row) * ldb + k0 + c * 8);
            if (PASSES == 3)
                cp16(dst + 32768, B_lo + (size_t)(n0 + row) * ldb + k0 + c * 8);
        }
        cp_commit();
    };

    const int lane = tid & 31;
    const int lr   = lane & 7;
    const int sub  = lane >> 3;
    const int warp = tid >> 5;
    const int wm   = warp >> 2, wn = warp & 3;

    const int a_row = wm * 64 + lr + (sub & 1) * 8;
    const int a_cad = sub >> 1;
    const int b_row = wn * 64 + lr + (sub >> 1) * 8;
    const int b_cad = sub & 1;

    float acc[4][8][4];
#pragma unroll
    for (int i = 0; i < 4; i++)
#pragma unroll
        for (int j = 0; j < 8; j++)
#pragma unroll
            for (int e = 0; e < 4; e++) acc[i][j][e] = 0.f;

    load_slab(0, 0);

    for (int s = 0; s < NSLAB; s++) {
        if (s + 1 < NSLAB) { load_slab((s + 1) * 64, (s + 1) & 1); cp_wait1(); }
        else               { cp_wait0(); }
        __syncthreads();

        const u32 sb = sbase + (s & 1) * STAGE;
#pragma unroll
        for (int kk = 0; kk < 4; kk++) {
            u32 bh[4][4], bl[4][4];
#pragma unroll
            for (int np = 0; np < 4; np++) {
                u32 badr = sb + 32768 + (b_row + np * 16) * 128
                         + (((kk * 2 + b_cad) ^ lr) << 4);
                ldsm4(badr, bh[np][0], bh[np][1], bh[np][2], bh[np][3]);
                if (PASSES == 3)
                    ldsm4(badr + 32768, bl[np][0], bl[np][1], bl[np][2], bl[np][3]);
            }
#pragma unroll
            for (int mt = 0; mt < 4; mt++) {
                u32 ah[4], al[4];
                u32 aadr = sb + (a_row + mt * 16) * 128
                         + (((kk * 2 + a_cad) ^ lr) << 4);
                ldsm4(aadr,         ah[0], ah[1], ah[2], ah[3]);
                ldsm4(aadr + 16384, al[0], al[1], al[2], al[3]);
#pragma unroll
                for (int np = 0; np < 4; np++) {
                    mma_bf16(acc[mt][2 * np],     ah, bh[np][0], bh[np][1]);
                    mma_bf16(acc[mt][2 * np + 1], ah, bh[np][2], bh[np][3]);
                    mma_bf16(acc[mt][2 * np],     al, bh[np][0], bh[np][1]);
                    mma_bf16(acc[mt][2 * np + 1], al, bh[np][2], bh[np][3]);
                    if (PASSES == 3) {
                        mma_bf16(acc[mt][2 * np],     ah, bl[np][0], bl[np][1]);
                        mma_bf16(acc[mt][2 * np + 1], ah, bl[np][2], bl[np][3]);
                    }
                }
            }
        }
        __syncthreads();
    }

    // ---------------- epilogues ----------------
    if (MODE == 1) {
        // write sim fp32, row stride CC
#pragma unroll
        for (int mt = 0; mt < 4; mt++) {
            int m = m0 + wm * 64 + mt * 16 + (lane >> 2);
#pragma unroll
            for (int jj = 0; jj < 8; jj++) {
                int d = n0 + wn * 64 + (lane & 3) * 2 + jj * 8;
                size_t i0 = ((size_t)b * CC + m) * CC + d;
                float2 v0; v0.x = acc[mt][jj][0]; v0.y = acc[mt][jj][1];
                float2 v1; v1.x = acc[mt][jj][2]; v1.y = acc[mt][jj][3];
                *(float2*)&g_sim[i0]          = v0;
                *(float2*)&g_sim[i0 + 8 * CC] = v1;
            }
        }
        return;
    }

    if (MODE == 3) {
        const float al_ = alpha[0];
#pragma unroll
        for (int mt = 0; mt < 4; mt++) {
            int m = m0 + wm * 64 + mt * 16 + (lane >> 2);
#pragma unroll
            for (int jj = 0; jj < 8; jj++) {
                int nn = n0 + wn * 64 + (lane & 3) * 2 + jj * 8;
                size_t b0i = ((size_t)b * CC + m) * NSEQ + nn;
                size_t b1i = b0i + 8 * NSEQ;
                float2 x0 = *(const float2*)&xres[b0i];
                float2 x1 = *(const float2*)&xres[b1i];
                float2 o0, o1;
                o0.x = al_ * acc[mt][jj][0] + x0.x;
                o0.y = al_ * acc[mt][jj][1] + x0.y;
                o1.x = al_ * acc[mt][jj][2] + x1.x;
                o1.y = al_ * acc[mt][jj][3] + x1.y;
                *(float2*)&Cout[b0i] = o0;
                *(float2*)&Cout[b1i] = o1;
            }
        }
        return;
    }

    // MODE 0 / MODE 2: bn + relu, transpose via smem, write bf16
    float sc[4][2], bs[4][2];
#pragma unroll
    for (int mt = 0; mt < 4; mt++)
#pragma unroll
        for (int h = 0; h < 2; h++) {
            int o = wm * 64 + mt * 16 + (lane >> 2) + h * 8;
            float g, be, mn, vr;
            if (MODE == 0) {
                if (o < 64) { g = gA[o]; be = bA[o]; mn = mA[o]; vr = vA[o]; }
                else        { g = gB[o - 64]; be = bB[o - 64]; mn = mB[o - 64]; vr = vB[o - 64]; }
            } else {
                int m = m0 + o;
                g = gA[m]; be = bA[m]; mn = mA[m]; vr = vA[m];
            }
            float s = g * rsqrtf(vr + EPS_BN);
            sc[mt][h] = s;
            bs[mt][h] = be - mn * s;
        }

    __nv_bfloat16* Th = (__nv_bfloat16*)smem;
    __nv_bfloat16* Tl = (__nv_bfloat16*)(smem + 69632);
    const int mloc = wm * 64 + (lane >> 2);
    const int nbas = wn * 64 + (lane & 3) * 2;
#pragma unroll
    for (int mt = 0; mt < 4; mt++)
#pragma unroll
        for (int jj = 0; jj < 8; jj++)
#pragma unroll
            for (int e = 0; e < 4; e++) {
                int h = e >> 1, col = e & 1;
                float val = fmaxf(acc[mt][jj][e] * sc[mt][h] + bs[mt][h], 0.f);
                int off = (nbas + jj * 8 + col) * 136 + mloc + mt * 16 + h * 8;
                if (MODE == 0) {
                    __nv_bfloat16 hi, lo; split_bf16(val, hi, lo);
                    Th[off] = hi;
                    Tl[off] = lo;
                } else {
                    Th[off] = __float2bfloat16(val);
                }
            }
    __syncthreads();

#pragma unroll
    for (int i = 0; i < 16; i++) {
        int idx = tid + i * 256;
        int n = idx >> 4, ch = idx & 15;
        uint4 hv = *(uint4*)&Th[n * 136 + ch * 8];
        if (MODE == 0) {
            uint4 lv = *(uint4*)&Tl[n * 136 + ch * 8];
            if (ch < 8) {
                size_t dst = ((size_t)b * CC + n0 + n) * DQ + ch * 8;
                *(uint4*)&g_qT_hi[dst] = hv;
                *(uint4*)&g_qT_lo[dst] = lv;
            } else {
                size_t dst = ((size_t)b * CC + n0 + n) * DQ + (ch - 8) * 8;
                *(uint4*)&g_kT_hi[dst] = hv;
                *(uint4*)&g_kT_lo[dst] = lv;
            }
        } else {
            size_t dst = ((size_t)b * NSEQ + n) * CC + m0 + ch * 8;
            *(uint4*)&g_vT_hi[dst] = hv;
        }
    }
}

// =====================================================================
// softmax: aff = softmax(-sim) over d; writes aff hi/lo bf16.
// one warp per row; grid (CC/8, BB), 256 threads
// =====================================================================
__global__ __launch_bounds__(256) void softmax_kernel()
{
    const int warp = threadIdx.x >> 5, lane = threadIdx.x & 31;
    const int row = blockIdx.x * 8 + warp;
    const int b   = blockIdx.y;

    const float4* src = (const float4*)(g_sim + ((size_t)b * CC + row) * CC);
    float z[32];
    float mx = -1e30f;
#pragma unroll
    for (int i = 0; i < 8; i++) {
        float4 v = src[lane + i * 32];
        z[i * 4 + 0] = -v.x; z[i * 4 + 1] = -v.y;
        z[i * 4 + 2] = -v.z; z[i * 4 + 3] = -v.w;
        mx = fmaxf(mx, fmaxf(fmaxf(z[i * 4], z[i * 4 + 1]),
                             fmaxf(z[i * 4 + 2], z[i * 4 + 3])));
    }
#pragma unroll
    for (int s = 16; s; s >>= 1) mx = fmaxf(mx, __shfl_xor_sync(~0u, mx, s));

    float sum = 0.f;
#pragma unroll
    for (int i = 0; i < 32; i++) { z[i] = __expf(z[i] - mx); sum += z[i]; }
#pragma unroll
    for (int s = 16; s; s >>= 1) sum += __shfl_xor_sync(~0u, sum, s);
    const float inv = 1.f / sum;

    uint2* dh = (uint2*)(g_aff_hi + ((size_t)b * CC + row) * CC);
    uint2* dl = (uint2*)(g_aff_lo + ((size_t)b * CC + row) * CC);
#pragma unroll
    for (int i = 0; i < 8; i++) {
        float a0 = z[i * 4] * inv, a1 = z[i * 4 + 1] * inv;
        float a2 = z[i * 4 + 2] * inv, a3 = z[i * 4 + 3] * inv;
        __nv_bfloat16 h0, l0, h1, l1, h2, l2, h3, l3;
        split_bf16(a0, h0, l0); split_bf16(a1, h1, l1);
        split_bf16(a2, h2, l2); split_bf16(a3, h3, l3);
        __nv_bfloat162 p;
        uint2 hv, lv;
        p.x = h0; p.y = h1; hv.x = *(u32*)&p;
        p.x = h2; p.y = h3; hv.y = *(u32*)&p;
        p.x = l0; p.y = l1; lv.x = *(u32*)&p;
        p.x = l2; p.y = l3; lv.y = *(u32*)&p;
        dh[lane + i * 32] = hv;
        dl[lane + i * 32] = lv;
    }
}

// =====================================================================
extern "C" void kernel_launch(void* const* d_in, const int* in_sizes, int n_in,
                              void* d_out, int out_size)
{
    const float* x    = (const float*)d_in[0];
    const float* Wq   = (const float*)d_in[1];
    const float* Wk   = (const float*)d_in[2];
    const float* Wv   = (const float*)d_in[3];
    const float* bn1g = (const float*)d_in[4];
    const float* bn1b = (const float*)d_in[5];
    const float* bn1m = (const float*)d_in[6];
    const float* bn1v = (const float*)d_in[7];
    const float* bn2g = (const float*)d_in[8];
    const float* bn2b = (const float*)d_in[9];
    const float* bn2m = (const float*)d_in[10];
    const float* bn2v = (const float*)d_in[11];
    const float* bn3g = (const float*)d_in[12];
    const float* bn3b = (const float*)d_in[13];
    const float* bn3m = (const float*)d_in[14];
    const float* bn3v = (const float*)d_in[15];
    const float* alpha= (const float*)d_in[16];
    float* out = (float*)d_out;

    cudaFuncSetAttribute(mma_gemm2<0,3,256>,  cudaFuncAttributeMaxDynamicSharedMemorySize, 196608);
    cudaFuncSetAttribute(mma_gemm2<1,3,64>,   cudaFuncAttributeMaxDynamicSharedMemorySize, 98304);
    cudaFuncSetAttribute(mma_gemm2<2,2,1024>, cudaFuncAttributeMaxDynamicSharedMemorySize, 131072);
    cudaFuncSetAttribute(mma_gemm2<3,2,1024>, cudaFuncAttributeMaxDynamicSharedMemorySize, 131072);

    convert_x<<<dim3(CC / 32, NSEQ / 32, BB), dim3(32, 8)>>>(x);
    convert_wv<<<CC * CC / 4 / 256, 256>>>(Wv);
    convert_wqk<<<128, 256>>>(Wq, Wk);

    // qk: q,k = relu(bn([Wq;Wk] . x^T)) -> qT/kT hi/lo
    mma_gemm2<0,3,256><<<dim3(4, 1, BB), 256, 196608>>>(
        nullptr, nullptr, bn1g, bn1b, bn1m, bn1v, bn2g, bn2b, bn2m, bn2v, nullptr);

    // sim = k^T q
    mma_gemm2<1,3,64><<<dim3(4, 8, BB), 256, 98304>>>(
        nullptr, nullptr, nullptr, nullptr, nullptr, nullptr,
        nullptr, nullptr, nullptr, nullptr, nullptr);

    softmax_kernel<<<dim3(CC / 8, BB), 256>>>();

    // v = relu(bn3(Wv . x)) -> vT_hi
    mma_gemm2<2,2,1024><<<dim3(1, 8, BB), 256, 131072>>>(
        nullptr, nullptr, bn3g, bn3b, bn3m, bn3v,
        nullptr, nullptr, nullptr, nullptr, nullptr);

    // out = alpha*(aff . v) + x
    mma_gemm2<3,2,1024><<<dim3(1, 8, BB), 256, 131072>>>(
        out, x, nullptr, nullptr, nullptr, nullptr,
        nullptr, nullptr, nullptr, nullptr, alpha);
}

// round 5
// speedup vs baseline: 4.7783x; 1.2228x over previous
#include <cuda_runtime.h>
#include <cuda_bf16.h>
#include <cstdint>

#define BB   32
#define CC   1024
#define NSEQ 256
#define DQ   64
#define EPS_BN 1e-5f

typedef unsigned long long u64;
typedef unsigned int u32;

// ---------------- scratch (static device memory) ----------------
__device__ __nv_bfloat16 g_x_hi[(size_t)BB * CC * NSEQ];    // 16 MB  x[b][c][n]
__device__ __nv_bfloat16 g_x_lo[(size_t)BB * CC * NSEQ];    // 16 MB
__device__ __nv_bfloat16 g_xT_hi[(size_t)BB * NSEQ * CC];   // 16 MB  x^T[b][n][c]
__device__ __nv_bfloat16 g_wv_hi[(size_t)CC * CC];          //  2 MB
__device__ __nv_bfloat16 g_wv_lo[(size_t)CC * CC];          //  2 MB
__device__ __nv_bfloat16 g_wqk_hi[128 * NSEQ];              // 64 KB  [Wq;Wk]
__device__ __nv_bfloat16 g_wqk_lo[128 * NSEQ];
__device__ __nv_bfloat16 g_qT_hi[(size_t)BB * CC * DQ];     //  4 MB  q^T[b][d][o]
__device__ __nv_bfloat16 g_qT_lo[(size_t)BB * CC * DQ];
__device__ __nv_bfloat16 g_kT_hi[(size_t)BB * CC * DQ];
__device__ __nv_bfloat16 g_kT_lo[(size_t)BB * CC * DQ];
__device__ __nv_bfloat16 g_aff_hi[(size_t)BB * CC * CC];    // 64 MB
__device__ __nv_bfloat16 g_vT_hi[(size_t)BB * NSEQ * CC];   // 16 MB  v^T[b][n][o]

// ---------------- helpers ----------------
__device__ __forceinline__ u32 smem_u32(const void* p) {
    u32 a;
    asm("{ .reg .u64 t; cvta.to.shared.u64 t, %1; cvt.u32.u64 %0, t; }"
        : "=r"(a) : "l"(p));
    return a;
}
__device__ __forceinline__ void split_bf16(float v, __nv_bfloat16& h, __nv_bfloat16& l) {
    h = __float2bfloat16(v);
    l = __float2bfloat16(v - __bfloat162float(h));
}
__device__ __forceinline__ void cp16(u32 dst, const void* src) {
    asm volatile("cp.async.cg.shared.global [%0], [%1], 16;" :: "r"(dst), "l"(src));
}
__device__ __forceinline__ void cp_commit() {
    asm volatile("cp.async.commit_group;" ::: "memory");
}
__device__ __forceinline__ void cp_wait1() {
    asm volatile("cp.async.wait_group 1;" ::: "memory");
}
__device__ __forceinline__ void cp_wait0() {
    asm volatile("cp.async.wait_group 0;" ::: "memory");
}
__device__ __forceinline__ void ldsm4(u32 addr, u32& r0, u32& r1, u32& r2, u32& r3) {
    asm volatile("ldmatrix.sync.aligned.m8n8.x4.shared.b16 {%0,%1,%2,%3}, [%4];"
                 : "=r"(r0), "=r"(r1), "=r"(r2), "=r"(r3) : "r"(addr));
}
__device__ __forceinline__ void mma_bf16(float* c, const u32* a, u32 b0, u32 b1) {
    asm volatile(
        "mma.sync.aligned.m16n8k16.row.col.f32.bf16.bf16.f32 "
        "{%0,%1,%2,%3}, {%4,%5,%6,%7}, {%8,%9}, {%0,%1,%2,%3};"
        : "+f"(c[0]), "+f"(c[1]), "+f"(c[2]), "+f"(c[3])
        : "r"(a[0]), "r"(a[1]), "r"(a[2]), "r"(a[3]), "r"(b0), "r"(b1));
}

// =====================================================================
// convert kernels
// =====================================================================
__global__ void convert_x(const float* __restrict__ x)
{
    __shared__ float t[32][33];
    const int tx = threadIdx.x, ty = threadIdx.y;
    const int c0 = blockIdx.x * 32, n0 = blockIdx.y * 32, b = blockIdx.z;

#pragma unroll
    for (int r = 0; r < 4; r++) {
        int row = ty + r * 8;
        size_t off = ((size_t)b * CC + c0 + row) * NSEQ + n0 + tx;
        float v = x[off];
        t[row][tx] = v;
        __nv_bfloat16 h, l; split_bf16(v, h, l);
        g_x_hi[off] = h;
        g_x_lo[off] = l;
    }
    __syncthreads();
#pragma unroll
    for (int r = 0; r < 4; r++) {
        int nrow = ty + r * 8;
        g_xT_hi[((size_t)b * NSEQ + n0 + nrow) * CC + c0 + tx] =
            __float2bfloat16(t[tx][nrow]);
    }
}

__global__ __launch_bounds__(256) void convert_wv(const float* __restrict__ W)
{
    size_t i = (size_t)blockIdx.x * 256 + threadIdx.x;
    float4 v = ((const float4*)W)[i];
    __nv_bfloat16 h0, l0, h1, l1, h2, l2, h3, l3;
    split_bf16(v.x, h0, l0); split_bf16(v.y, h1, l1);
    split_bf16(v.z, h2, l2); split_bf16(v.w, h3, l3);
    __nv_bfloat162* hp = (__nv_bfloat162*)g_wv_hi;
    __nv_bfloat162* lp = (__nv_bfloat162*)g_wv_lo;
    __nv_bfloat162 a; a.x = h0; a.y = h1;
    __nv_bfloat162 bq; bq.x = h2; bq.y = h3;
    hp[i * 2] = a; hp[i * 2 + 1] = bq;
    a.x = l0; a.y = l1; bq.x = l2; bq.y = l3;
    lp[i * 2] = a; lp[i * 2 + 1] = bq;
}

__global__ __launch_bounds__(256) void convert_wqk(
    const float* __restrict__ Wq, const float* __restrict__ Wk)
{
    int r = blockIdx.x;
    const float* src = (r < 64) ? (Wq + (size_t)r * NSEQ) : (Wk + (size_t)(r - 64) * NSEQ);
    float v = src[threadIdx.x];
    __nv_bfloat16 h, l; split_bf16(v, h, l);
    g_wqk_hi[r * NSEQ + threadIdx.x] = h;
    g_wqk_lo[r * NSEQ + threadIdx.x] = l;
}

// =====================================================================
// unified mma.sync GEMM: C[128 x 256] tile, slab=64, double buffered.
// MODE 0 (P3): qk.  A=[Wq;Wk] hi/lo  B=x hi/lo      -> bn+relu, qT/kT hi/lo
// MODE 2 (P2): v.   A=Wv hi/lo       B=xT_hi        -> bn3+relu, vT_hi
// MODE 3 (P1): out. A=aff_hi         B=vT_hi        -> alpha*.+x, d_out
// grid (N/256, M/128, BB)
// =====================================================================
template<int MODE, int PASSES, int KTOT>
__global__ void __launch_bounds__(256, 1) mma_gemm2(
    float* __restrict__ Cout, const float* __restrict__ xres,
    const float* __restrict__ gA, const float* __restrict__ bA,
    const float* __restrict__ mA, const float* __restrict__ vA,
    const float* __restrict__ gB, const float* __restrict__ bB,
    const float* __restrict__ mB, const float* __restrict__ vB,
    const float* __restrict__ alpha)
{
    constexpr int STAGE = (PASSES == 3) ? 98304 : ((PASSES == 2) ? 65536 : 49152);
    constexpr int BOFF  = (PASSES == 1) ? 16384 : 32768;
    constexpr int NSLAB = KTOT / 64;

    extern __shared__ __align__(1024) char smem[];
    const u32 sbase = smem_u32(smem);
    const int tid = threadIdx.x;
    const int b   = blockIdx.z;
    const int n0  = blockIdx.x * 256;
    const int m0  = blockIdx.y * 128;

    int lda, ldb;
    const __nv_bfloat16 *A_hi, *A_lo = nullptr, *B_hi, *B_lo = nullptr;
    if (MODE == 0) {
        A_hi = g_wqk_hi; A_lo = g_wqk_lo;
        B_hi = g_x_hi + (size_t)b * CC * NSEQ;
        B_lo = g_x_lo + (size_t)b * CC * NSEQ;
        lda = NSEQ; ldb = NSEQ;
    } else if (MODE == 2) {
        A_hi = g_wv_hi; A_lo = g_wv_lo;
        B_hi = g_xT_hi + (size_t)b * NSEQ * CC;
        lda = CC; ldb = CC;
    } else {
        A_hi = g_aff_hi + (size_t)b * CC * CC;
        B_hi = g_vT_hi + (size_t)b * NSEQ * CC;
        lda = CC; ldb = CC;
    }

    auto load_slab = [&](int k0, int buf) {
        const u32 sb = sbase + buf * STAGE;
#pragma unroll
        for (int i = 0; i < 4; i++) {               // A: 128 rows x 8 chunks
            int idx = tid + i * 256;
            int row = idx >> 3, c = idx & 7;
            u32 dst = sb + row * 128 + ((c ^ (row & 7)) << 4);
            cp16(dst, A_hi + (size_t)(m0 + row) * lda + k0 + c * 8);
            if (PASSES >= 2)
                cp16(dst + 16384, A_lo + (size_t)(m0 + row) * lda + k0 + c * 8);
        }
#pragma unroll
        for (int i = 0; i < 8; i++) {               // B: 256 rows x 8 chunks
            int idx = tid + i * 256;
            int row = idx >> 3, c = idx & 7;
            u32 dst = sb + BOFF + row * 128 + ((c ^ (row & 7)) << 4);
            cp16(dst, B_hi + (size_t)(n0 + row) * ldb + k0 + c * 8);
            if (PASSES == 3)
                cp16(dst + 32768, B_lo + (size_t)(n0 + row) * ldb + k0 + c * 8);
        }
        cp_commit();
    };

    const int lane = tid & 31;
    const int lr   = lane & 7;
    const int sub  = lane >> 3;
    const int warp = tid >> 5;
    const int wm   = warp >> 2, wn = warp & 3;

    const int a_row = wm * 64 + lr + (sub & 1) * 8;
    const int a_cad = sub >> 1;
    const int b_row = wn * 64 + lr + (sub >> 1) * 8;
    const int b_cad = sub & 1;

    float acc[4][8][4];
#pragma unroll
    for (int i = 0; i < 4; i++)
#pragma unroll
        for (int j = 0; j < 8; j++)
#pragma unroll
            for (int e = 0; e < 4; e++) acc[i][j][e] = 0.f;

    load_slab(0, 0);

    for (int s = 0; s < NSLAB; s++) {
        if (s + 1 < NSLAB) { load_slab((s + 1) * 64, (s + 1) & 1); cp_wait1(); }
        else               { cp_wait0(); }
        __syncthreads();

        const u32 sb = sbase + (s & 1) * STAGE;
#pragma unroll
        for (int kk = 0; kk < 4; kk++) {
            u32 bh[4][4], bl[4][4];
#pragma unroll
            for (int np = 0; np < 4; np++) {
                u32 badr = sb + BOFF + (b_row + np * 16) * 128
                         + (((kk * 2 + b_cad) ^ lr) << 4);
                ldsm4(badr, bh[np][0], bh[np][1], bh[np][2], bh[np][3]);
                if (PASSES == 3)
                    ldsm4(badr + 32768, bl[np][0], bl[np][1], bl[np][2], bl[np][3]);
            }
#pragma unroll
            for (int mt = 0; mt < 4; mt++) {
                u32 ah[4], al[4];
                u32 aadr = sb + (a_row + mt * 16) * 128
                         + (((kk * 2 + a_cad) ^ lr) << 4);
                ldsm4(aadr, ah[0], ah[1], ah[2], ah[3]);
                if (PASSES >= 2)
                    ldsm4(aadr + 16384, al[0], al[1], al[2], al[3]);
#pragma unroll
                for (int np = 0; np < 4; np++) {
                    mma_bf16(acc[mt][2 * np],     ah, bh[np][0], bh[np][1]);
                    mma_bf16(acc[mt][2 * np + 1], ah, bh[np][2], bh[np][3]);
                    if (PASSES >= 2) {
                        mma_bf16(acc[mt][2 * np],     al, bh[np][0], bh[np][1]);
                        mma_bf16(acc[mt][2 * np + 1], al, bh[np][2], bh[np][3]);
                    }
                    if (PASSES == 3) {
                        mma_bf16(acc[mt][2 * np],     ah, bl[np][0], bl[np][1]);
                        mma_bf16(acc[mt][2 * np + 1], ah, bl[np][2], bl[np][3]);
                    }
                }
            }
        }
        __syncthreads();
    }

    // ---------------- epilogues ----------------
    if (MODE == 3) {
        const float al_ = alpha[0];
#pragma unroll
        for (int mt = 0; mt < 4; mt++) {
            int m = m0 + wm * 64 + mt * 16 + (lane >> 2);
#pragma unroll
            for (int jj = 0; jj < 8; jj++) {
                int nn = n0 + wn * 64 + (lane & 3) * 2 + jj * 8;
                size_t b0i = ((size_t)b * CC + m) * NSEQ + nn;
                size_t b1i = b0i + 8 * NSEQ;
                float2 x0 = *(const float2*)&xres[b0i];
                float2 x1 = *(const float2*)&xres[b1i];
                float2 o0, o1;
                o0.x = al_ * acc[mt][jj][0] + x0.x;
                o0.y = al_ * acc[mt][jj][1] + x0.y;
                o1.x = al_ * acc[mt][jj][2] + x1.x;
                o1.y = al_ * acc[mt][jj][3] + x1.y;
                *(float2*)&Cout[b0i] = o0;
                *(float2*)&Cout[b1i] = o1;
            }
        }
        return;
    }

    // MODE 0 / MODE 2: bn + relu, transpose via smem, write bf16
    float sc[4][2], bs[4][2];
#pragma unroll
    for (int mt = 0; mt < 4; mt++)
#pragma unroll
        for (int h = 0; h < 2; h++) {
            int o = wm * 64 + mt * 16 + (lane >> 2) + h * 8;
            float g, be, mn, vr;
            if (MODE == 0) {
                if (o < 64) { g = gA[o]; be = bA[o]; mn = mA[o]; vr = vA[o]; }
                else        { g = gB[o - 64]; be = bB[o - 64]; mn = mB[o - 64]; vr = vB[o - 64]; }
            } else {
                int m = m0 + o;
                g = gA[m]; be = bA[m]; mn = mA[m]; vr = vA[m];
            }
            float s = g * rsqrtf(vr + EPS_BN);
            sc[mt][h] = s;
            bs[mt][h] = be - mn * s;
        }

    __nv_bfloat16* Th = (__nv_bfloat16*)smem;
    __nv_bfloat16* Tl = (__nv_bfloat16*)(smem + 69632);
    const int mloc = wm * 64 + (lane >> 2);
    const int nbas = wn * 64 + (lane & 3) * 2;
#pragma unroll
    for (int mt = 0; mt < 4; mt++)
#pragma unroll
        for (int jj = 0; jj < 8; jj++)
#pragma unroll
            for (int e = 0; e < 4; e++) {
                int h = e >> 1, col = e & 1;
                float val = fmaxf(acc[mt][jj][e] * sc[mt][h] + bs[mt][h], 0.f);
                int off = (nbas + jj * 8 + col) * 136 + mloc + mt * 16 + h * 8;
                if (MODE == 0) {
                    __nv_bfloat16 hi, lo; split_bf16(val, hi, lo);
                    Th[off] = hi;
                    Tl[off] = lo;
                } else {
                    Th[off] = __float2bfloat16(val);
                }
            }
    __syncthreads();

#pragma unroll
    for (int i = 0; i < 16; i++) {
        int idx = tid + i * 256;
        int n = idx >> 4, ch = idx & 15;
        uint4 hv = *(uint4*)&Th[n * 136 + ch * 8];
        if (MODE == 0) {
            uint4 lv = *(uint4*)&Tl[n * 136 + ch * 8];
            if (ch < 8) {
                size_t dst = ((size_t)b * CC + n0 + n) * DQ + ch * 8;
                *(uint4*)&g_qT_hi[dst] = hv;
                *(uint4*)&g_qT_lo[dst] = lv;
            } else {
                size_t dst = ((size_t)b * CC + n0 + n) * DQ + (ch - 8) * 8;
                *(uint4*)&g_kT_hi[dst] = hv;
                *(uint4*)&g_kT_lo[dst] = lv;
            }
        } else {
            size_t dst = ((size_t)b * NSEQ + n) * CC + m0 + ch * 8;
            *(uint4*)&g_vT_hi[dst] = hv;
        }
    }
}

// =====================================================================
// fused sim + softmax: CTA = 32 c-rows x 1024 d-cols, K=64, 3-pass HMMA.
// sim[c][d] = sum_o kT[c][o] qT[d][o];  aff = softmax(-sim) -> aff_hi bf16.
// 8 warps, warp w covers cols {h*512 + w*64 .. +64} for h in {0,1}.
// smem: A (kT hi/lo) 8KB @0; B (qT hi/lo, 512 rows/half) 128KB @8192.
// grid (CC/32, BB)
// =====================================================================
#define FS_SMEM (8192 + 131072)

__global__ void __launch_bounds__(256, 1) sim_softmax_fused()
{
    extern __shared__ __align__(1024) char smem[];
    const u32 sbase = smem_u32(smem);
    const int tid  = threadIdx.x;
    const int lane = tid & 31;
    const int lr   = lane & 7;
    const int sub  = lane >> 3;
    const int w    = tid >> 5;
    const int b    = blockIdx.y;
    const int c0   = blockIdx.x * 32;

    const __nv_bfloat16* Ah = g_kT_hi + ((size_t)b * CC + c0) * DQ;
    const __nv_bfloat16* Al = g_kT_lo + ((size_t)b * CC + c0) * DQ;
    const __nv_bfloat16* Bh = g_qT_hi + (size_t)b * CC * DQ;
    const __nv_bfloat16* Bl = g_qT_lo + (size_t)b * CC * DQ;

    // load A (once): 32 rows x 8 chunks = 256
    {
        int row = tid >> 3, c = tid & 7;
        u32 dst = sbase + row * 128 + ((c ^ (row & 7)) << 4);
        cp16(dst,        Ah + (size_t)row * DQ + c * 8);
        cp16(dst + 4096, Al + (size_t)row * DQ + c * 8);
    }

    const int a_row = lr + (sub & 1) * 8;
    const int a_cad = sub >> 1;
    const int b_row = lr + (sub >> 1) * 8;
    const int b_cad = sub & 1;

    float acc[2][16][4];
#pragma unroll
    for (int i = 0; i < 2; i++)
#pragma unroll
        for (int j = 0; j < 16; j++)
#pragma unroll
            for (int e = 0; e < 4; e++) acc[i][j][e] = 0.f;

    for (int half = 0; half < 2; half++) {
        // load B half: 512 rows x 8 chunks = 4096 (hi) + 4096 (lo)
#pragma unroll
        for (int i = 0; i < 16; i++) {
            int idx = tid + i * 256;
            int row = idx >> 3, c = idx & 7;
            u32 dst = sbase + 8192 + row * 128 + ((c ^ (row & 7)) << 4);
            cp16(dst,         Bh + (size_t)(half * 512 + row) * DQ + c * 8);
            cp16(dst + 65536, Bl + (size_t)(half * 512 + row) * DQ + c * 8);
        }
        cp_commit();
        cp_wait0();
        __syncthreads();

#pragma unroll
        for (int kk = 0; kk < 4; kk++) {
            u32 ah[2][4], al[2][4];
#pragma unroll
            for (int mt = 0; mt < 2; mt++) {
                u32 aadr = sbase + (a_row + mt * 16) * 128
                         + (((kk * 2 + a_cad) ^ lr) << 4);
                ldsm4(aadr,        ah[mt][0], ah[mt][1], ah[mt][2], ah[mt][3]);
                ldsm4(aadr + 4096, al[mt][0], al[mt][1], al[mt][2], al[mt][3]);
            }
#pragma unroll
            for (int jt = 0; jt < 4; jt++) {
                u32 bh[4], bl[4];
                u32 badr = sbase + 8192 + (b_row + w * 64 + jt * 16) * 128
                         + (((kk * 2 + b_cad) ^ lr) << 4);
                ldsm4(badr,         bh[0], bh[1], bh[2], bh[3]);
                ldsm4(badr + 65536, bl[0], bl[1], bl[2], bl[3]);
                int jj = half * 8 + jt * 2;
#pragma unroll
                for (int mt = 0; mt < 2; mt++) {
                    mma_bf16(acc[mt][jj],     ah[mt], bh[0], bh[1]);
                    mma_bf16(acc[mt][jj + 1], ah[mt], bh[2], bh[3]);
                    mma_bf16(acc[mt][jj],     al[mt], bh[0], bh[1]);
                    mma_bf16(acc[mt][jj + 1], al[mt], bh[2], bh[3]);
                    mma_bf16(acc[mt][jj],     ah[mt], bl[0], bl[1]);
                    mma_bf16(acc[mt][jj + 1], ah[mt], bl[2], bl[3]);
                }
            }
        }
        __syncthreads();
    }

    // ---- row stats across warps (A smem area is dead now) ----
    float* rs  = (float*)smem;                 // [32][8]
    float* fst = (float*)(smem + 1024);        // [32]

    // rows this thread holds: r(mt,h) = mt*16 + (lane>>2) + h*8
    float m[2][2];
#pragma unroll
    for (int mt = 0; mt < 2; mt++)
#pragma unroll
        for (int h = 0; h < 2; h++) {
            float mm = -1e30f;
#pragma unroll
            for (int jj = 0; jj < 16; jj++)
                mm = fmaxf(mm, fmaxf(-acc[mt][jj][2 * h], -acc[mt][jj][2 * h + 1]));
            m[mt][h] = mm;
        }
#pragma unroll
    for (int s = 1; s <= 2; s <<= 1) {
#pragma unroll
        for (int mt = 0; mt < 2; mt++)
#pragma unroll
            for (int h = 0; h < 2; h++)
                m[mt][h] = fmaxf(m[mt][h], __shfl_xor_sync(~0u, m[mt][h], s));
    }
    if ((lane & 3) == 0) {
#pragma unroll
        for (int mt = 0; mt < 2; mt++)
#pragma unroll
            for (int h = 0; h < 2; h++)
                rs[(mt * 16 + (lane >> 2) + h * 8) * 8 + w] = m[mt][h];
    }
    __syncthreads();
    if (tid < 32) {
        float v = rs[tid * 8];
#pragma unroll
        for (int i = 1; i < 8; i++) v = fmaxf(v, rs[tid * 8 + i]);
        fst[tid] = v;
    }
    __syncthreads();

    float sm[2][2];
#pragma unroll
    for (int mt = 0; mt < 2; mt++)
#pragma unroll
        for (int h = 0; h < 2; h++) {
            float fm = fst[mt * 16 + (lane >> 2) + h * 8];
            float ss = 0.f;
#pragma unroll
            for (int jj = 0; jj < 16; jj++) {
                float e0 = __expf(-acc[mt][jj][2 * h]     - fm);
                float e1 = __expf(-acc[mt][jj][2 * h + 1] - fm);
                acc[mt][jj][2 * h]     = e0;
                acc[mt][jj][2 * h + 1] = e1;
                ss += e0 + e1;
            }
            sm[mt][h] = ss;
        }
#pragma unroll
    for (int s = 1; s <= 2; s <<= 1) {
#pragma unroll
        for (int mt = 0; mt < 2; mt++)
#pragma unroll
            for (int h = 0; h < 2; h++)
                sm[mt][h] += __shfl_xor_sync(~0u, sm[mt][h], s);
    }
    __syncthreads();   // all reads of rs (max) done before overwrite
    if ((lane & 3) == 0) {
#pragma unroll
        for (int mt = 0; mt < 2; mt++)
#pragma unroll
            for (int h = 0; h < 2; h++)
                rs[(mt * 16 + (lane >> 2) + h * 8) * 8 + w] = sm[mt][h];
    }
    __syncthreads();
    if (tid < 32) {
        float v = rs[tid * 8];
#pragma unroll
        for (int i = 1; i < 8; i++) v += rs[tid * 8 + i];
        fst[tid] = 1.0f / v;
    }
    __syncthreads();

    // ---- stage scaled bf16 into smem (B area dead), then coalesced write ----
    __nv_bfloat16* st = (__nv_bfloat16*)(smem + 8192);   // [32][1048] padded
#pragma unroll
    for (int mt = 0; mt < 2; mt++)
#pragma unroll
        for (int h = 0; h < 2; h++) {
            int r = mt * 16 + (lane >> 2) + h * 8;
            float inv = fst[r];
#pragma unroll
            for (int jj = 0; jj < 16; jj++) {
                int col = (jj >> 3) * 512 + w * 64 + (jj & 7) * 8 + (lane & 3) * 2;
                __nv_bfloat162 p;
                p.x = __float2bfloat16(acc[mt][jj][2 * h] * inv);
                p.y = __float2bfloat16(acc[mt][jj][2 * h + 1] * inv);
                *(__nv_bfloat162*)&st[r * 1048 + col] = p;
            }
        }
    __syncthreads();

#pragma unroll
    for (int i = 0; i < 16; i++) {
        int idx = tid + i * 256;
        int row = idx >> 7, u4 = idx & 127;
        uint4 v = *(uint4*)&st[row * 1048 + u4 * 8];
        *(uint4*)&g_aff_hi[((size_t)b * CC + c0 + row) * CC + u4 * 8] = v;
    }
}

// =====================================================================
extern "C" void kernel_launch(void* const* d_in, const int* in_sizes, int n_in,
                              void* d_out, int out_size)
{
    const float* x    = (const float*)d_in[0];
    const float* Wq   = (const float*)d_in[1];
    const float* Wk   = (const float*)d_in[2];
    const float* Wv   = (const float*)d_in[3];
    const float* bn1g = (const float*)d_in[4];
    const float* bn1b = (const float*)d_in[5];
    const float* bn1m = (const float*)d_in[6];
    const float* bn1v = (const float*)d_in[7];
    const float* bn2g = (const float*)d_in[8];
    const float* bn2b = (const float*)d_in[9];
    const float* bn2m = (const float*)d_in[10];
    const float* bn2v = (const float*)d_in[11];
    const float* bn3g = (const float*)d_in[12];
    const float* bn3b = (const float*)d_in[13];
    const float* bn3m = (const float*)d_in[14];
    const float* bn3v = (const float*)d_in[15];
    const float* alpha= (const float*)d_in[16];
    float* out = (float*)d_out;

    cudaFuncSetAttribute(mma_gemm2<0,3,256>,  cudaFuncAttributeMaxDynamicSharedMemorySize, 196608);
    cudaFuncSetAttribute(mma_gemm2<2,2,1024>, cudaFuncAttributeMaxDynamicSharedMemorySize, 131072);
    cudaFuncSetAttribute(mma_gemm2<3,1,1024>, cudaFuncAttributeMaxDynamicSharedMemorySize, 98304);
    cudaFuncSetAttribute(sim_softmax_fused,   cudaFuncAttributeMaxDynamicSharedMemorySize, FS_SMEM);

    convert_x<<<dim3(CC / 32, NSEQ / 32, BB), dim3(32, 8)>>>(x);
    convert_wv<<<CC * CC / 4 / 256, 256>>>(Wv);
    convert_wqk<<<128, 256>>>(Wq, Wk);

    // qk: q,k = relu(bn([Wq;Wk] . x^T)) -> qT/kT hi/lo
    mma_gemm2<0,3,256><<<dim3(4, 1, BB), 256, 196608>>>(
        nullptr, nullptr, bn1g, bn1b, bn1m, bn1v, bn2g, bn2b, bn2m, bn2v, nullptr);

    // v = relu(bn3(Wv . x)) -> vT_hi
    mma_gemm2<2,2,1024><<<dim3(1, 8, BB), 256, 131072>>>(
        nullptr, nullptr, bn3g, bn3b, bn3m, bn3v,
        nullptr, nullptr, nullptr, nullptr, nullptr);

    // sim + softmax fused -> aff_hi
    sim_softmax_fused<<<dim3(CC / 32, BB), 256, FS_SMEM>>>();

    // out = alpha*(aff . v) + x
    mma_gemm2<3,1,1024><<<dim3(1, 8, BB), 256, 98304>>>(
        out, x, nullptr, nullptr, nullptr, nullptr,
        nullptr, nullptr, nullptr, nullptr, alpha);
}

// round 6
// speedup vs baseline: 5.6677x; 1.1861x over previous
#include <cuda_runtime.h>
#include <cuda_bf16.h>
#include <cstdint>

#define BB   32
#define CC   1024
#define NSEQ 256
#define DQ   64
#define EPS_BN 1e-5f

typedef unsigned long long u64;
typedef unsigned int u32;

// ---------------- scratch (static device memory) ----------------
__device__ __nv_bfloat16 g_x_hi[(size_t)BB * CC * NSEQ];    // 16 MB  x[b][c][n]
__device__ __nv_bfloat16 g_x_lo[(size_t)BB * CC * NSEQ];    // 16 MB
__device__ __nv_bfloat16 g_xT_hi[(size_t)BB * NSEQ * CC];   // 16 MB  x^T[b][n][c]
__device__ __nv_bfloat16 g_wv_hi[(size_t)CC * CC];          //  2 MB
__device__ __nv_bfloat16 g_wqk_hi[128 * NSEQ];              // 64 KB  [Wq;Wk]
__device__ __nv_bfloat16 g_wqk_lo[128 * NSEQ];
__device__ __nv_bfloat16 g_qT_hi[(size_t)BB * CC * DQ];     //  4 MB  q^T[b][d][o]
__device__ __nv_bfloat16 g_qT_lo[(size_t)BB * CC * DQ];
__device__ __nv_bfloat16 g_kT_hi[(size_t)BB * CC * DQ];
__device__ __nv_bfloat16 g_kT_lo[(size_t)BB * CC * DQ];
__device__ __nv_bfloat16 g_aff_hi[(size_t)BB * CC * CC];    // 64 MB
__device__ __nv_bfloat16 g_vT_hi[(size_t)BB * NSEQ * CC];   // 16 MB  v^T[b][n][o]

// ---------------- helpers ----------------
__device__ __forceinline__ u32 smem_u32(const void* p) {
    u32 a;
    asm("{ .reg .u64 t; cvta.to.shared.u64 t, %1; cvt.u32.u64 %0, t; }"
        : "=r"(a) : "l"(p));
    return a;
}
__device__ __forceinline__ void split_bf16(float v, __nv_bfloat16& h, __nv_bfloat16& l) {
    h = __float2bfloat16(v);
    l = __float2bfloat16(v - __bfloat162float(h));
}
__device__ __forceinline__ void cp16(u32 dst, const void* src) {
    asm volatile("cp.async.cg.shared.global [%0], [%1], 16;" :: "r"(dst), "l"(src));
}
__device__ __forceinline__ void cp_commit() {
    asm volatile("cp.async.commit_group;" ::: "memory");
}
__device__ __forceinline__ void cp_wait1() {
    asm volatile("cp.async.wait_group 1;" ::: "memory");
}
__device__ __forceinline__ void cp_wait0() {
    asm volatile("cp.async.wait_group 0;" ::: "memory");
}
__device__ __forceinline__ void ldsm4(u32 addr, u32& r0, u32& r1, u32& r2, u32& r3) {
    asm volatile("ldmatrix.sync.aligned.m8n8.x4.shared.b16 {%0,%1,%2,%3}, [%4];"
                 : "=r"(r0), "=r"(r1), "=r"(r2), "=r"(r3) : "r"(addr));
}
__device__ __forceinline__ void mma_bf16(float* c, const u32* a, u32 b0, u32 b1) {
    asm volatile(
        "mma.sync.aligned.m16n8k16.row.col.f32.bf16.bf16.f32 "
        "{%0,%1,%2,%3}, {%4,%5,%6,%7}, {%8,%9}, {%0,%1,%2,%3};"
        : "+f"(c[0]), "+f"(c[1]), "+f"(c[2]), "+f"(c[3])
        : "r"(a[0]), "r"(a[1]), "r"(a[2]), "r"(a[3]), "r"(b0), "r"(b1));
}

// =====================================================================
// convert kernels
// =====================================================================
__global__ void convert_x(const float* __restrict__ x)
{
    __shared__ float t[32][33];
    const int tx = threadIdx.x, ty = threadIdx.y;
    const int c0 = blockIdx.x * 32, n0 = blockIdx.y * 32, b = blockIdx.z;

#pragma unroll
    for (int r = 0; r < 4; r++) {
        int row = ty + r * 8;
        size_t off = ((size_t)b * CC + c0 + row) * NSEQ + n0 + tx;
        float v = x[off];
        t[row][tx] = v;
        __nv_bfloat16 h, l; split_bf16(v, h, l);
        g_x_hi[off] = h;
        g_x_lo[off] = l;
    }
    __syncthreads();
#pragma unroll
    for (int r = 0; r < 4; r++) {
        int nrow = ty + r * 8;
        g_xT_hi[((size_t)b * NSEQ + n0 + nrow) * CC + c0 + tx] =
            __float2bfloat16(t[tx][nrow]);
    }
}

__global__ __launch_bounds__(256) void convert_wv(const float* __restrict__ W)
{
    size_t i = (size_t)blockIdx.x * 256 + threadIdx.x;
    float4 v = ((const float4*)W)[i];
    __nv_bfloat162* hp = (__nv_bfloat162*)g_wv_hi;
    __nv_bfloat162 a; a.x = __float2bfloat16(v.x); a.y = __float2bfloat16(v.y);
    __nv_bfloat162 bq; bq.x = __float2bfloat16(v.z); bq.y = __float2bfloat16(v.w);
    hp[i * 2] = a; hp[i * 2 + 1] = bq;
}

__global__ __launch_bounds__(256) void convert_wqk(
    const float* __restrict__ Wq, const float* __restrict__ Wk)
{
    int r = blockIdx.x;
    const float* src = (r < 64) ? (Wq + (size_t)r * NSEQ) : (Wk + (size_t)(r - 64) * NSEQ);
    float v = src[threadIdx.x];
    __nv_bfloat16 h, l; split_bf16(v, h, l);
    g_wqk_hi[r * NSEQ + threadIdx.x] = h;
    g_wqk_lo[r * NSEQ + threadIdx.x] = l;
}

// =====================================================================
// unified mma.sync GEMM: C[128 x 256] tile, slab=64, double buffered.
// MODE 0 (P3): qk.  A=[Wq;Wk] hi/lo  B=x hi/lo      -> bn+relu, qT/kT hi/lo
// MODE 2 (P1): v.   A=Wv_hi          B=xT_hi        -> bn3+relu, vT_hi
// MODE 3 (P1): out. A=aff_hi         B=vT_hi        -> alpha*.+x, d_out
// grid (N/256, M/128, BB)
// =====================================================================
template<int MODE, int PASSES, int KTOT>
__global__ void __launch_bounds__(256, 1) mma_gemm2(
    float* __restrict__ Cout, const float* __restrict__ xres,
    const float* __restrict__ gA, const float* __restrict__ bA,
    const float* __restrict__ mA, const float* __restrict__ vA,
    const float* __restrict__ gB, const float* __restrict__ bB,
    const float* __restrict__ mB, const float* __restrict__ vB,
    const float* __restrict__ alpha)
{
    constexpr int STAGE = (PASSES == 3) ? 98304 : ((PASSES == 2) ? 65536 : 49152);
    constexpr int BOFF  = (PASSES == 1) ? 16384 : 32768;
    constexpr int NSLAB = KTOT / 64;

    extern __shared__ __align__(1024) char smem[];
    const u32 sbase = smem_u32(smem);
    const int tid = threadIdx.x;
    const int b   = blockIdx.z;
    const int n0  = blockIdx.x * 256;
    const int m0  = blockIdx.y * 128;

    int lda, ldb;
    const __nv_bfloat16 *A_hi, *A_lo = nullptr, *B_hi, *B_lo = nullptr;
    if (MODE == 0) {
        A_hi = g_wqk_hi; A_lo = g_wqk_lo;
        B_hi = g_x_hi + (size_t)b * CC * NSEQ;
        B_lo = g_x_lo + (size_t)b * CC * NSEQ;
        lda = NSEQ; ldb = NSEQ;
    } else if (MODE == 2) {
        A_hi = g_wv_hi;
        B_hi = g_xT_hi + (size_t)b * NSEQ * CC;
        lda = CC; ldb = CC;
    } else {
        A_hi = g_aff_hi + (size_t)b * CC * CC;
        B_hi = g_vT_hi + (size_t)b * NSEQ * CC;
        lda = CC; ldb = CC;
    }

    auto load_slab = [&](int k0, int buf) {
        const u32 sb = sbase + buf * STAGE;
#pragma unroll
        for (int i = 0; i < 4; i++) {               // A: 128 rows x 8 chunks
            int idx = tid + i * 256;
            int row = idx >> 3, c = idx & 7;
            u32 dst = sb + row * 128 + ((c ^ (row & 7)) << 4);
            cp16(dst, A_hi + (size_t)(m0 + row) * lda + k0 + c * 8);
            if (PASSES >= 2)
                cp16(dst + 16384, A_lo + (size_t)(m0 + row) * lda + k0 + c * 8);
        }
#pragma unroll
        for (int i = 0; i < 8; i++) {               // B: 256 rows x 8 chunks
            int idx = tid + i * 256;
            int row = idx >> 3, c = idx & 7;
            u32 dst = sb + BOFF + row * 128 + ((c ^ (row & 7)) << 4);
            cp16(dst, B_hi + (size_t)(n0 + row) * ldb + k0 + c * 8);
            if (PASSES == 3)
                cp16(dst + 32768, B_lo + (size_t)(n0 + row) * ldb + k0 + c * 8);
        }
        cp_commit();
    };

    const int lane = tid & 31;
    const int lr   = lane & 7;
    const int sub  = lane >> 3;
    const int warp = tid >> 5;
    const int wm   = warp >> 2, wn = warp & 3;

    const int a_row = wm * 64 + lr + (sub & 1) * 8;
    const int a_cad = sub >> 1;
    const int b_row = wn * 64 + lr + (sub >> 1) * 8;
    const int b_cad = sub & 1;

    float acc[4][8][4];
#pragma unroll
    for (int i = 0; i < 4; i++)
#pragma unroll
        for (int j = 0; j < 8; j++)
#pragma unroll
            for (int e = 0; e < 4; e++) acc[i][j][e] = 0.f;

    load_slab(0, 0);

    for (int s = 0; s < NSLAB; s++) {
        if (s + 1 < NSLAB) { load_slab((s + 1) * 64, (s + 1) & 1); cp_wait1(); }
        else               { cp_wait0(); }
        __syncthreads();

        const u32 sb = sbase + (s & 1) * STAGE;
#pragma unroll
        for (int kk = 0; kk < 4; kk++) {
            u32 bh[4][4], bl[4][4];
#pragma unroll
            for (int np = 0; np < 4; np++) {
                u32 badr = sb + BOFF + (b_row + np * 16) * 128
                         + (((kk * 2 + b_cad) ^ lr) << 4);
                ldsm4(badr, bh[np][0], bh[np][1], bh[np][2], bh[np][3]);
                if (PASSES == 3)
                    ldsm4(badr + 32768, bl[np][0], bl[np][1], bl[np][2], bl[np][3]);
            }
#pragma unroll
            for (int mt = 0; mt < 4; mt++) {
                u32 ah[4], al[4];
                u32 aadr = sb + (a_row + mt * 16) * 128
                         + (((kk * 2 + a_cad) ^ lr) << 4);
                ldsm4(aadr, ah[0], ah[1], ah[2], ah[3]);
                if (PASSES >= 2)
                    ldsm4(aadr + 16384, al[0], al[1], al[2], al[3]);
#pragma unroll
                for (int np = 0; np < 4; np++) {
                    mma_bf16(acc[mt][2 * np],     ah, bh[np][0], bh[np][1]);
                    mma_bf16(acc[mt][2 * np + 1], ah, bh[np][2], bh[np][3]);
                    if (PASSES >= 2) {
                        mma_bf16(acc[mt][2 * np],     al, bh[np][0], bh[np][1]);
                        mma_bf16(acc[mt][2 * np + 1], al, bh[np][2], bh[np][3]);
                    }
                    if (PASSES == 3) {
                        mma_bf16(acc[mt][2 * np],     ah, bl[np][0], bl[np][1]);
                        mma_bf16(acc[mt][2 * np + 1], ah, bl[np][2], bl[np][3]);
                    }
                }
            }
        }
        __syncthreads();
    }

    // ---------------- epilogues ----------------
    if (MODE == 3) {
        const float al_ = alpha[0];
#pragma unroll
        for (int mt = 0; mt < 4; mt++) {
            int m = m0 + wm * 64 + mt * 16 + (lane >> 2);
#pragma unroll
            for (int jj = 0; jj < 8; jj++) {
                int nn = n0 + wn * 64 + (lane & 3) * 2 + jj * 8;
                size_t b0i = ((size_t)b * CC + m) * NSEQ + nn;
                size_t b1i = b0i + 8 * NSEQ;
                float2 x0 = *(const float2*)&xres[b0i];
                float2 x1 = *(const float2*)&xres[b1i];
                float2 o0, o1;
                o0.x = al_ * acc[mt][jj][0] + x0.x;
                o0.y = al_ * acc[mt][jj][1] + x0.y;
                o1.x = al_ * acc[mt][jj][2] + x1.x;
                o1.y = al_ * acc[mt][jj][3] + x1.y;
                *(float2*)&Cout[b0i] = o0;
                *(float2*)&Cout[b1i] = o1;
            }
        }
        return;
    }

    // MODE 0 / MODE 2: bn + relu, transpose via smem, write bf16
    float sc[4][2], bs[4][2];
#pragma unroll
    for (int mt = 0; mt < 4; mt++)
#pragma unroll
        for (int h = 0; h < 2; h++) {
            int o = wm * 64 + mt * 16 + (lane >> 2) + h * 8;
            float g, be, mn, vr;
            if (MODE == 0) {
                if (o < 64) { g = gA[o]; be = bA[o]; mn = mA[o]; vr = vA[o]; }
                else        { g = gB[o - 64]; be = bB[o - 64]; mn = mB[o - 64]; vr = vB[o - 64]; }
            } else {
                int m = m0 + o;
                g = gA[m]; be = bA[m]; mn = mA[m]; vr = vA[m];
            }
            float s = g * rsqrtf(vr + EPS_BN);
            sc[mt][h] = s;
            bs[mt][h] = be - mn * s;
        }

    __nv_bfloat16* Th = (__nv_bfloat16*)smem;
    __nv_bfloat16* Tl = (__nv_bfloat16*)(smem + 69632);
    const int mloc = wm * 64 + (lane >> 2);
    const int nbas = wn * 64 + (lane & 3) * 2;
#pragma unroll
    for (int mt = 0; mt < 4; mt++)
#pragma unroll
        for (int jj = 0; jj < 8; jj++)
#pragma unroll
            for (int e = 0; e < 4; e++) {
                int h = e >> 1, col = e & 1;
                float val = fmaxf(acc[mt][jj][e] * sc[mt][h] + bs[mt][h], 0.f);
                int off = (nbas + jj * 8 + col) * 136 + mloc + mt * 16 + h * 8;
                if (MODE == 0) {
                    __nv_bfloat16 hi, lo; split_bf16(val, hi, lo);
                    Th[off] = hi;
                    Tl[off] = lo;
                } else {
                    Th[off] = __float2bfloat16(val);
                }
            }
    __syncthreads();

#pragma unroll
    for (int i = 0; i < 16; i++) {
        int idx = tid + i * 256;
        int n = idx >> 4, ch = idx & 15;
        uint4 hv = *(uint4*)&Th[n * 136 + ch * 8];
        if (MODE == 0) {
            uint4 lv = *(uint4*)&Tl[n * 136 + ch * 8];
            if (ch < 8) {
                size_t dst = ((size_t)b * CC + n0 + n) * DQ + ch * 8;
                *(uint4*)&g_qT_hi[dst] = hv;
                *(uint4*)&g_qT_lo[dst] = lv;
            } else {
                size_t dst = ((size_t)b * CC + n0 + n) * DQ + (ch - 8) * 8;
                *(uint4*)&g_kT_hi[dst] = hv;
                *(uint4*)&g_kT_lo[dst] = lv;
            }
        } else {
            size_t dst = ((size_t)b * NSEQ + n) * CC + m0 + ch * 8;
            *(uint4*)&g_vT_hi[dst] = hv;
        }
    }
}

// =====================================================================
// fused sim + softmax: CTA = 32 c-rows x 1024 d-cols, K=64, 3-pass HMMA.
// Pipelined: 4 slabs of 256 B-rows, double-buffered (64KB per buffer).
// 8 warps; within a slab warp w covers cols w*32..w*32+32.
// jj layout: jj = slab*4 + jt*2 + n8 -> col = slab*256 + w*32 + jt*16 + n8*8.
// smem: A (kT hi/lo) 8KB @0; B buffers @8192 (hi @+0, lo @+32768), x2.
// grid (CC/32, BB)
// =====================================================================
#define FS_SMEM (8192 + 131072)

__global__ void __launch_bounds__(256, 1) sim_softmax_fused()
{
    extern __shared__ __align__(1024) char smem[];
    const u32 sbase = smem_u32(smem);
    const int tid  = threadIdx.x;
    const int lane = tid & 31;
    const int lr   = lane & 7;
    const int sub  = lane >> 3;
    const int w    = tid >> 5;
    const int b    = blockIdx.y;
    const int c0   = blockIdx.x * 32;

    const __nv_bfloat16* Ah = g_kT_hi + ((size_t)b * CC + c0) * DQ;
    const __nv_bfloat16* Al = g_kT_lo + ((size_t)b * CC + c0) * DQ;
    const __nv_bfloat16* Bh = g_qT_hi + (size_t)b * CC * DQ;
    const __nv_bfloat16* Bl = g_qT_lo + (size_t)b * CC * DQ;

    auto load_slab = [&](int slab, int buf) {
        const u32 sb = sbase + 8192 + buf * 65536;
#pragma unroll
        for (int i = 0; i < 8; i++) {
            int idx = tid + i * 256;
            int row = idx >> 3, c = idx & 7;
            u32 dst = sb + row * 128 + ((c ^ (row & 7)) << 4);
            cp16(dst,         Bh + (size_t)(slab * 256 + row) * DQ + c * 8);
            cp16(dst + 32768, Bl + (size_t)(slab * 256 + row) * DQ + c * 8);
        }
        cp_commit();
    };

    // group 0: A + slab 0
    {
        int row = tid >> 3, c = tid & 7;
        u32 dst = sbase + row * 128 + ((c ^ (row & 7)) << 4);
        cp16(dst,        Ah + (size_t)row * DQ + c * 8);
        cp16(dst + 4096, Al + (size_t)row * DQ + c * 8);
    }
    load_slab(0, 0);

    const int a_row = lr + (sub & 1) * 8;
    const int a_cad = sub >> 1;
    const int b_row = lr + (sub >> 1) * 8;
    const int b_cad = sub & 1;

    float acc[2][16][4];
#pragma unroll
    for (int i = 0; i < 2; i++)
#pragma unroll
        for (int j = 0; j < 16; j++)
#pragma unroll
            for (int e = 0; e < 4; e++) acc[i][j][e] = 0.f;

    for (int s = 0; s < 4; s++) {
        if (s + 1 < 4) { load_slab(s + 1, (s + 1) & 1); cp_wait1(); }
        else           { cp_wait0(); }
        __syncthreads();

        const u32 sb = sbase + 8192 + (s & 1) * 65536;
#pragma unroll
        for (int kk = 0; kk < 4; kk++) {
            u32 ah[2][4], al[2][4];
#pragma unroll
            for (int mt = 0; mt < 2; mt++) {
                u32 aadr = sbase + (a_row + mt * 16) * 128
                         + (((kk * 2 + a_cad) ^ lr) << 4);
                ldsm4(aadr,        ah[mt][0], ah[mt][1], ah[mt][2], ah[mt][3]);
                ldsm4(aadr + 4096, al[mt][0], al[mt][1], al[mt][2], al[mt][3]);
            }
#pragma unroll
            for (int jt = 0; jt < 2; jt++) {
                u32 bh[4], bl[4];
                u32 badr = sb + (b_row + w * 32 + jt * 16) * 128
                         + (((kk * 2 + b_cad) ^ lr) << 4);
                ldsm4(badr,         bh[0], bh[1], bh[2], bh[3]);
                ldsm4(badr + 32768, bl[0], bl[1], bl[2], bl[3]);
                int jj = s * 4 + jt * 2;
#pragma unroll
                for (int mt = 0; mt < 2; mt++) {
                    mma_bf16(acc[mt][jj],     ah[mt], bh[0], bh[1]);
                    mma_bf16(acc[mt][jj + 1], ah[mt], bh[2], bh[3]);
                    mma_bf16(acc[mt][jj],     al[mt], bh[0], bh[1]);
                    mma_bf16(acc[mt][jj + 1], al[mt], bh[2], bh[3]);
                    mma_bf16(acc[mt][jj],     ah[mt], bl[0], bl[1]);
                    mma_bf16(acc[mt][jj + 1], ah[mt], bl[2], bl[3]);
                }
            }
        }
        __syncthreads();
    }

    // ---- row stats across warps (A smem area is dead now) ----
    float* rs  = (float*)smem;                 // [32][8]
    float* fst = (float*)(smem + 1024);        // [32]

    float m[2][2];
#pragma unroll
    for (int mt = 0; mt < 2; mt++)
#pragma unroll
        for (int h = 0; h < 2; h++) {
            float mm = -1e30f;
#pragma unroll
            for (int jj = 0; jj < 16; jj++)
                mm = fmaxf(mm, fmaxf(-acc[mt][jj][2 * h], -acc[mt][jj][2 * h + 1]));
            m[mt][h] = mm;
        }
#pragma unroll
    for (int s = 1; s <= 2; s <<= 1) {
#pragma unroll
        for (int mt = 0; mt < 2; mt++)
#pragma unroll
            for (int h = 0; h < 2; h++)
                m[mt][h] = fmaxf(m[mt][h], __shfl_xor_sync(~0u, m[mt][h], s));
    }
    if ((lane & 3) == 0) {
#pragma unroll
        for (int mt = 0; mt < 2; mt++)
#pragma unroll
            for (int h = 0; h < 2; h++)
                rs[(mt * 16 + (lane >> 2) + h * 8) * 8 + w] = m[mt][h];
    }
    __syncthreads();
    if (tid < 32) {
        float v = rs[tid * 8];
#pragma unroll
        for (int i = 1; i < 8; i++) v = fmaxf(v, rs[tid * 8 + i]);
        fst[tid] = v;
    }
    __syncthreads();

    float sm[2][2];
#pragma unroll
    for (int mt = 0; mt < 2; mt++)
#pragma unroll
        for (int h = 0; h < 2; h++) {
            float fm = fst[mt * 16 + (lane >> 2) + h * 8];
            float ss = 0.f;
#pragma unroll
            for (int jj = 0; jj < 16; jj++) {
                float e0 = __expf(-acc[mt][jj][2 * h]     - fm);
                float e1 = __expf(-acc[mt][jj][2 * h + 1] - fm);
                acc[mt][jj][2 * h]     = e0;
                acc[mt][jj][2 * h + 1] = e1;
                ss += e0 + e1;
            }
            sm[mt][h] = ss;
        }
#pragma unroll
    for (int s = 1; s <= 2; s <<= 1) {
#pragma unroll
        for (int mt = 0; mt < 2; mt++)
#pragma unroll
            for (int h = 0; h < 2; h++)
                sm[mt][h] += __shfl_xor_sync(~0u, sm[mt][h], s);
    }
    __syncthreads();
    if ((lane & 3) == 0) {
#pragma unroll
        for (int mt = 0; mt < 2; mt++)
#pragma unroll
            for (int h = 0; h < 2; h++)
                rs[(mt * 16 + (lane >> 2) + h * 8) * 8 + w] = sm[mt][h];
    }
    __syncthreads();
    if (tid < 32) {
        float v = rs[tid * 8];
#pragma unroll
        for (int i = 1; i < 8; i++) v += rs[tid * 8 + i];
        fst[tid] = 1.0f / v;
    }
    __syncthreads();

    // ---- stage scaled bf16 into smem (B area dead), then coalesced write ----
    __nv_bfloat16* st = (__nv_bfloat16*)(smem + 8192);   // [32][1048] padded
#pragma unroll
    for (int mt = 0; mt < 2; mt++)
#pragma unroll
        for (int h = 0; h < 2; h++) {
            int r = mt * 16 + (lane >> 2) + h * 8;
            float inv = fst[r];
#pragma unroll
            for (int jj = 0; jj < 16; jj++) {
                int col = (jj >> 2) * 256 + w * 32 + ((jj >> 1) & 1) * 16
                        + (jj & 1) * 8 + (lane & 3) * 2;
                __nv_bfloat162 p;
                p.x = __float2bfloat16(acc[mt][jj][2 * h] * inv);
                p.y = __float2bfloat16(acc[mt][jj][2 * h + 1] * inv);
                *(__nv_bfloat162*)&st[r * 1048 + col] = p;
            }
        }
    __syncthreads();

#pragma unroll
    for (int i = 0; i < 16; i++) {
        int idx = tid + i * 256;
        int row = idx >> 7, u4 = idx & 127;
        uint4 v = *(uint4*)&st[row * 1048 + u4 * 8];
        *(uint4*)&g_aff_hi[((size_t)b * CC + c0 + row) * CC + u4 * 8] = v;
    }
}

// =====================================================================
extern "C" void kernel_launch(void* const* d_in, const int* in_sizes, int n_in,
                              void* d_out, int out_size)
{
    const float* x    = (const float*)d_in[0];
    const float* Wq   = (const float*)d_in[1];
    const float* Wk   = (const float*)d_in[2];
    const float* Wv   = (const float*)d_in[3];
    const float* bn1g = (const float*)d_in[4];
    const float* bn1b = (const float*)d_in[5];
    const float* bn1m = (const float*)d_in[6];
    const float* bn1v = (const float*)d_in[7];
    const float* bn2g = (const float*)d_in[8];
    const float* bn2b = (const float*)d_in[9];
    const float* bn2m = (const float*)d_in[10];
    const float* bn2v = (const float*)d_in[11];
    const float* bn3g = (const float*)d_in[12];
    const float* bn3b = (const float*)d_in[13];
    const float* bn3m = (const float*)d_in[14];
    const float* bn3v = (const float*)d_in[15];
    const float* alpha= (const float*)d_in[16];
    float* out = (float*)d_out;

    cudaFuncSetAttribute(mma_gemm2<0,3,256>,  cudaFuncAttributeMaxDynamicSharedMemorySize, 196608);
    cudaFuncSetAttribute(mma_gemm2<2,1,1024>, cudaFuncAttributeMaxDynamicSharedMemorySize, 98304);
    cudaFuncSetAttribute(mma_gemm2<3,1,1024>, cudaFuncAttributeMaxDynamicSharedMemorySize, 98304);
    cudaFuncSetAttribute(sim_softmax_fused,   cudaFuncAttributeMaxDynamicSharedMemorySize, FS_SMEM);

    convert_x<<<dim3(CC / 32, NSEQ / 32, BB), dim3(32, 8)>>>(x);
    convert_wv<<<CC * CC / 4 / 256, 256>>>(Wv);
    convert_wqk<<<128, 256>>>(Wq, Wk);

    // qk: q,k = relu(bn([Wq;Wk] . x^T)) -> qT/kT hi/lo
    mma_gemm2<0,3,256><<<dim3(4, 1, BB), 256, 196608>>>(
        nullptr, nullptr, bn1g, bn1b, bn1m, bn1v, bn2g, bn2b, bn2m, bn2v, nullptr);

    // v = relu(bn3(Wv . x)) -> vT_hi   (1-pass bf16)
    mma_gemm2<2,1,1024><<<dim3(1, 8, BB), 256, 98304>>>(
        nullptr, nullptr, bn3g, bn3b, bn3m, bn3v,
        nullptr, nullptr, nullptr, nullptr, nullptr);

    // sim + softmax fused -> aff_hi
    sim_softmax_fused<<<dim3(CC / 32, BB), 256, FS_SMEM>>>();

    // out = alpha*(aff . v) + x
    mma_gemm2<3,1,1024><<<dim3(1, 8, BB), 256, 98304>>>(
        out, x, nullptr, nullptr, nullptr, nullptr,
        nullptr, nullptr, nullptr, nullptr, alpha);
}